// round 6
// baseline (speedup 1.0000x reference)
#include <cuda_runtime.h>
#include <cuda_bf16.h>
#include <cstdint>

// ---------------- problem constants ----------------
constexpr int T_ = 64, N_ = 40, D_ = 4, H_ = 256, R_ = 64;
constexpr int E_ = N_ * (N_ - 1);        // 1560
constexpr int TE = T_ * E_;              // 99840
constexpr int TN = T_ * N_;              // 2560

// ---------------- scratch ----------------
// split bf16 activation buffers (hi/lo)
__device__ __align__(16) __nv_bfloat16 g_nbh[TN * H_], g_nbl[TN * H_];   // mlp1fc1 / mlp3fc1 out
__device__ __align__(16) __nv_bfloat16 g_h1h[TN * H_], g_h1l[TN * H_];
__device__ __align__(16) __nv_bfloat16 g_nsh[TN * H_], g_nsl[TN * H_];
__device__ __align__(16) __nv_bfloat16 g_n3h[TN * H_], g_n3l[TN * H_];
__device__ __align__(16) __nv_bfloat16 g_tmph[TE * H_], g_tmpl[TE * H_]; // mlp2fc1 / mlp4fc1 out
__device__ __align__(16) __nv_bfloat16 g_e2h[TE * H_], g_e2l[TE * H_];
__device__ __align__(16) __nv_bfloat16 g_e4h[TE * H_], g_e4l[TE * H_];
// split weights (one big arena, offsets below)
constexpr int WOFF_M1W2 = 0;
constexpr int WOFF_M2W1 = 65536;
constexpr int WOFF_M2W2 = 196608;
constexpr int WOFF_M3W1 = 262144;
constexpr int WOFF_M3W2 = 327680;
constexpr int WOFF_M4W1 = 393216;
constexpr int WOFF_M4W2 = 589824;
constexpr int WOFF_FWIH = 655360;
constexpr int WOFF_RWIH = 720896;
constexpr int WTOTAL    = 786432;
__device__ __align__(16) __nv_bfloat16 g_whi[WTOTAL], g_wlo[WTOTAL];
// fp32 buffers
__device__ float g_gf[TE * H_];
__device__ float g_gr[TE * H_];
__device__ float g_hf[TE * R_];
__device__ float g_hr[TE * R_];
__device__ int   g_rlist[N_ * (N_ - 1)];

__device__ __forceinline__ float eluf(float v) { return v > 0.f ? v : expm1f(v); }
__device__ __forceinline__ float sigmf(float v) { return 1.f / (1.f + expf(-v)); }

__device__ __forceinline__ void bsplit2(float x0, float x1, uint32_t& hi, uint32_t& lo) {
    asm("cvt.rn.bf16x2.f32 %0, %1, %2;" : "=r"(hi) : "f"(x1), "f"(x0));
    __nv_bfloat162 h = *reinterpret_cast<__nv_bfloat162*>(&hi);
    float r0 = x0 - __bfloat162float(h.x);
    float r1 = x1 - __bfloat162float(h.y);
    asm("cvt.rn.bf16x2.f32 %0, %1, %2;" : "=r"(lo) : "f"(r1), "f"(r0));
}

__device__ __forceinline__ void mma_bf16(float* d, const uint32_t* a, const uint32_t* b) {
    asm volatile(
        "mma.sync.aligned.m16n8k16.row.col.f32.bf16.bf16.f32 "
        "{%0,%1,%2,%3},{%4,%5,%6,%7},{%8,%9},{%0,%1,%2,%3};"
        : "+f"(d[0]), "+f"(d[1]), "+f"(d[2]), "+f"(d[3])
        : "r"(a[0]), "r"(a[1]), "r"(a[2]), "r"(a[3]), "r"(b[0]), "r"(b[1]));
}

__device__ __forceinline__ void ldsm4(uint32_t& r0, uint32_t& r1, uint32_t& r2, uint32_t& r3,
                                      uint32_t addr) {
    asm volatile("ldmatrix.sync.aligned.m8n8.x4.shared.b16 {%0,%1,%2,%3}, [%4];"
                 : "=r"(r0), "=r"(r1), "=r"(r2), "=r"(r3) : "r"(addr));
}

__device__ __forceinline__ uint32_t smem_u32(const void* p) {
    uint32_t a;
    asm("{ .reg .u64 t; cvta.to.shared.u64 t, %1; cvt.u32.u64 %0, t; }" : "=r"(a) : "l"(p));
    return a;
}

#define CP16(dst, src) \
    asm volatile("cp.async.cg.shared.global [%0], [%1], 16;" :: "r"(dst), "l"(src))
#define CPCOMMIT() asm volatile("cp.async.commit_group;")
#define CPWAIT1()  asm volatile("cp.async.wait_group 1;")

// ---------------- weight split (once per launch, tiny) ----------------
__global__ void splitk(const float* __restrict__ in, __nv_bfloat16* __restrict__ oh,
                       __nv_bfloat16* __restrict__ ol, int n) {
    int i = blockIdx.x * blockDim.x + threadIdx.x;
    if (i >= n) return;
    float v = in[i];
    __nv_bfloat16 h = __float2bfloat16(v);
    oh[i] = h;
    ol[i] = __float2bfloat16(v - __bfloat162float(h));
}

// ---------------- mlp1 fc1 (K=4, tiny) -> split out ----------------
__global__ void mlp1_fc1(const float* __restrict__ x, const float* __restrict__ W1,
                         const float* __restrict__ b1) {
    int idx = blockIdx.x * blockDim.x + threadIdx.x;
    int row = idx >> 8;
    int j = idx & 255;
    const float* xr = x + row * D_;
    const float* w = W1 + j * D_;
    float v = b1[j] + xr[0] * w[0] + xr[1] * w[1] + xr[2] * w[2] + xr[3] * w[3];
    v = eluf(v);
    __nv_bfloat16 h = __float2bfloat16(v);
    g_nbh[idx] = h;
    g_nbl[idx] = __float2bfloat16(v - __bfloat162float(h));
}

// ---------------- build per-node incoming edge lists ----------------
__global__ void build_rlist(const int* __restrict__ recv) {
    int n = threadIdx.x;
    if (n >= N_) return;
    int p = 0;
    for (int e = 0; e < E_; e++)
        if (recv[e] == n) g_rlist[n * (N_ - 1) + p++] = e;
}

// ---------------- edge2node scatter-add (split in, split out) ----------------
__global__ void edge2node() {
    int b = blockIdx.x;
    int t = b / N_;
    int n = b - t * N_;
    int c = threadIdx.x;
    const int* lst = g_rlist + n * (N_ - 1);
    float s = 0.f;
#pragma unroll 13
    for (int i = 0; i < N_ - 1; i++) {
        int e = lst[i];
        size_t idx = ((size_t)t * E_ + e) * H_ + c;
        s += __bfloat162float(g_e2h[idx]) + __bfloat162float(g_e2l[idx]);
    }
    __nv_bfloat16 h = __float2bfloat16(s);
    g_nsh[(size_t)b * H_ + c] = h;
    g_nsl[(size_t)b * H_ + c] = __float2bfloat16(s - __bfloat162float(h));
}

// ------- bf16x3 tensor-core GEMM: pre-split inputs, cp.async 3-stage pipeline -------
// Block 128(M) x 256(N full), 8 warps of 64x64, k-chunk 32 elements.
// MODE 0: plain A; MODE 1: gather send|recv (Kd=512); MODE 2: send|recv|skip (Kd=768)
// OUT 0: fp32 + bias + bias2, no act (LSTM gates). OUT 1: ELU + split bf16 out.
// smem rows: 32 bf16 (64B) + 16B pad = 80B stride; ldmatrix conflict-free.
constexpr int STAGES = 3;
constexpr int A_HI = 0;
constexpr int A_LO = 10240;           // 128*80
constexpr int B_HI = 20480;
constexpr int B_LO = 40960;           // +256*80
constexpr int STAGE_BYTES = 61440;
constexpr int GEMM_SMEM = STAGES * STAGE_BYTES;   // 184320

template <int MODE, int OUT>
__global__ __launch_bounds__(256) void gemm_tc(
    const __nv_bfloat16* __restrict__ Ah, const __nv_bfloat16* __restrict__ Al,
    const __nv_bfloat16* __restrict__ Wh, const __nv_bfloat16* __restrict__ Wl,
    const float* __restrict__ bias, const float* __restrict__ bias2,
    float* __restrict__ Cf, __nv_bfloat16* __restrict__ Ch, __nv_bfloat16* __restrict__ Cl,
    int Kd,
    const int* __restrict__ send, const int* __restrict__ recv,
    const __nv_bfloat16* __restrict__ s0h, const __nv_bfloat16* __restrict__ s0l,
    const __nv_bfloat16* __restrict__ s1h, const __nv_bfloat16* __restrict__ s1l) {
    extern __shared__ __align__(128) char smem[];
    const uint32_t sb = smem_u32(smem);

    const int tid = threadIdx.x;
    const int bm = blockIdx.x * 128;
    const int warp = tid >> 5, lane = tid & 31;

    // ---- global load roles ----
    const int arow = tid >> 1, half = tid & 1;   // A row, 16-elem half of 32-elem chunk
    const __nv_bfloat16 *arh = nullptr, *arl = nullptr;
    const __nv_bfloat16 *a0h = nullptr, *a0l = nullptr, *a1h = nullptr, *a1l = nullptr;
    const __nv_bfloat16 *a2h = nullptr, *a2l = nullptr;
    {
        int m = bm + arow;
        if (MODE == 0) {
            arh = Ah + (size_t)m * Kd;
            arl = Al + (size_t)m * Kd;
        } else {
            int t = m / E_;
            int e = m - t * E_;
            size_t so = ((size_t)t * N_ + send[e]) * H_;
            size_t ro = ((size_t)t * N_ + recv[e]) * H_;
            a0h = s0h + so; a0l = s0l + so;
            a1h = s0h + ro; a1l = s0l + ro;
            if (MODE == 2) { a2h = s1h + (size_t)m * H_; a2l = s1l + (size_t)m * H_; }
        }
    }
    const __nv_bfloat16* wrh = Wh + (size_t)tid * Kd;
    const __nv_bfloat16* wrl = Wl + (size_t)tid * Kd;

    // ---- ldmatrix addressing ----
    const int mi = lane >> 3, rowin = lane & 7;
    const int rsel = (mi & 1) * 8 + rowin;
    const int kh16 = (mi >> 1) * 16;             // byte offset: which 8-elem k half
    const int wm = (warp >> 2) * 64;
    const int wn = (warp & 3) * 64;

    float acc[4][8][4];
#pragma unroll
    for (int i = 0; i < 4; i++)
#pragma unroll
        for (int j = 0; j < 8; j++)
#pragma unroll
            for (int k = 0; k < 4; k++) acc[i][j][k] = 0.f;

    const uint32_t a_sts = (uint32_t)(arow * 80 + half * 32);
    const uint32_t b_sts = (uint32_t)(tid * 80);

    auto issue = [&](int chunk) {
        const int stg = chunk % STAGES;
        const uint32_t su = sb + stg * STAGE_BYTES;
        int kb = chunk * 32 + half * 16;
        const __nv_bfloat16 *ph, *pl;
        if (MODE == 0) {
            ph = arh + kb; pl = arl + kb;
        } else {
            int off = kb & 255;
            if (MODE == 1) {
                ph = (kb < 256 ? a0h : a1h) + off;
                pl = (kb < 256 ? a0l : a1l) + off;
            } else {
                ph = (kb < 256 ? a0h : (kb < 512 ? a1h : a2h)) + off;
                pl = (kb < 256 ? a0l : (kb < 512 ? a1l : a2l)) + off;
            }
        }
        uint32_t ad = su + A_HI + a_sts;
        CP16(ad, ph); CP16(ad + 16, ph + 8);
        ad += (A_LO - A_HI);
        CP16(ad, pl); CP16(ad + 16, pl + 8);
        const __nv_bfloat16* bph = wrh + chunk * 32;
        const __nv_bfloat16* bpl = wrl + chunk * 32;
        uint32_t bd = su + B_HI + b_sts;
        CP16(bd, bph); CP16(bd + 16, bph + 8); CP16(bd + 32, bph + 16); CP16(bd + 48, bph + 24);
        bd += (B_LO - B_HI);
        CP16(bd, bpl); CP16(bd + 16, bpl + 8); CP16(bd + 32, bpl + 16); CP16(bd + 48, bpl + 24);
    };

    const int nchunks = Kd >> 5;
    issue(0); CPCOMMIT();
    if (nchunks > 1) issue(1);
    CPCOMMIT();

    for (int chunk = 0; chunk < nchunks; chunk++) {
        CPWAIT1();
        __syncthreads();
        int pf = chunk + 2;
        if (pf < nchunks) issue(pf);
        CPCOMMIT();

        const uint32_t st = sb + (chunk % STAGES) * STAGE_BYTES;
#pragma unroll
        for (int ks = 0; ks < 2; ks++) {
            const uint32_t kbase = (uint32_t)(ks * 32 + kh16);
            uint32_t ah[4][4], al[4][4];
#pragma unroll
            for (int mf = 0; mf < 4; mf++) {
                uint32_t ad = st + A_HI + (uint32_t)((wm + mf * 16 + rsel) * 80) + kbase;
                ldsm4(ah[mf][0], ah[mf][1], ah[mf][2], ah[mf][3], ad);
                ldsm4(al[mf][0], al[mf][1], al[mf][2], al[mf][3], ad + (A_LO - A_HI));
            }
#pragma unroll
            for (int bt = 0; bt < 4; bt++) {
                uint32_t bh[4], bl[4];
                uint32_t bd = st + B_HI + (uint32_t)((wn + bt * 16 + rsel) * 80) + kbase;
                ldsm4(bh[0], bh[1], bh[2], bh[3], bd);
                ldsm4(bl[0], bl[1], bl[2], bl[3], bd + (B_LO - B_HI));
#pragma unroll
                for (int s = 0; s < 2; s++) {
                    uint32_t bhp[2] = {bh[s], bh[s + 2]};
                    uint32_t blp[2] = {bl[s], bl[s + 2]};
#pragma unroll
                    for (int mf = 0; mf < 4; mf++) {
                        float* ac = acc[mf][bt * 2 + s];
                        mma_bf16(ac, ah[mf], bhp);
                        mma_bf16(ac, ah[mf], blp);
                        mma_bf16(ac, al[mf], bhp);
                    }
                }
            }
        }
    }

    // ---- epilogue ----
    const int grp = lane >> 2, q = lane & 3;
#pragma unroll
    for (int mf = 0; mf < 4; mf++) {
        int r0 = bm + wm + mf * 16 + grp;
        int r1 = r0 + 8;
#pragma unroll
        for (int j8 = 0; j8 < 8; j8++) {
            int col = wn + j8 * 8 + q * 2;
            float b0 = bias[col], b1 = bias[col + 1];
            if (OUT == 0) { b0 += bias2[col]; b1 += bias2[col + 1]; }
            float x0 = acc[mf][j8][0] + b0;
            float x1 = acc[mf][j8][1] + b1;
            float x2 = acc[mf][j8][2] + b0;
            float x3 = acc[mf][j8][3] + b1;
            if (OUT == 1) {
                x0 = eluf(x0); x1 = eluf(x1); x2 = eluf(x2); x3 = eluf(x3);
                uint32_t h01, l01, h23, l23;
                bsplit2(x0, x1, h01, l01);
                bsplit2(x2, x3, h23, l23);
                *(uint32_t*)(Ch + (size_t)r0 * 256 + col) = h01;
                *(uint32_t*)(Cl + (size_t)r0 * 256 + col) = l01;
                *(uint32_t*)(Ch + (size_t)r1 * 256 + col) = h23;
                *(uint32_t*)(Cl + (size_t)r1 * 256 + col) = l23;
            } else {
                *(float2*)(Cf + (size_t)r0 * 256 + col) = make_float2(x0, x1);
                *(float2*)(Cf + (size_t)r1 * 256 + col) = make_float2(x2, x3);
            }
        }
    }
}

// ---------------- fused bidirectional LSTM (recurrence only) ----------------
constexpr int LSTM_GROUPS = E_ / 8;
constexpr int LSTM_SMEM = 64 * 256 * 4 + 64 * 8 * 4;

__global__ __launch_bounds__(64) void lstm_kernel(
    const float* __restrict__ gf, const float* __restrict__ gr,
    const float* __restrict__ fWhh, const float* __restrict__ rWhh,
    float* __restrict__ hfOut, float* __restrict__ hrOut) {
    extern __shared__ float sm[];
    float* Wq = sm;
    float4* hsm4 = (float4*)(sm + 64 * 256);

    int dir; int grp;
    const float* gates; const float* Whh; float* hout;
    if (blockIdx.x < LSTM_GROUPS) {
        dir = 0; grp = blockIdx.x; gates = gf; Whh = fWhh; hout = hfOut;
    } else {
        dir = 1; grp = blockIdx.x - LSTM_GROUPS; gates = gr; Whh = rWhh; hout = hrOut;
    }
    const int j = threadIdx.x;

    for (int idx = j; idx < 64 * 256; idx += 64) {
        int k = idx >> 8;
        int rem = idx & 255;
        int jj = rem >> 2;
        int q = rem & 3;
        Wq[idx] = Whh[(q * 64 + jj) * 64 + k];
    }
    for (int i = j; i < 128; i += 64) hsm4[i] = make_float4(0.f, 0.f, 0.f, 0.f);

    const int e0 = grp * 8;
    float c[8];
#pragma unroll
    for (int e = 0; e < 8; e++) c[e] = 0.f;
    __syncthreads();

    for (int s = 0; s < T_; s++) {
        int t = dir ? (T_ - 1 - s) : s;
        float a0[8], a1[8], a2[8], a3[8];
#pragma unroll
        for (int e = 0; e < 8; e++) {
            const float* gp = gates + ((size_t)t * E_ + e0 + e) * 256;
            a0[e] = gp[j]; a1[e] = gp[64 + j]; a2[e] = gp[128 + j]; a3[e] = gp[192 + j];
        }
#pragma unroll 16
        for (int k = 0; k < 64; k++) {
            float4 w  = *(const float4*)&Wq[k * 256 + j * 4];
            float4 hA = hsm4[k * 2 + 0];
            float4 hB = hsm4[k * 2 + 1];
            float hv[8] = {hA.x, hA.y, hA.z, hA.w, hB.x, hB.y, hB.z, hB.w};
#pragma unroll
            for (int e = 0; e < 8; e++) {
                a0[e] = fmaf(hv[e], w.x, a0[e]);
                a1[e] = fmaf(hv[e], w.y, a1[e]);
                a2[e] = fmaf(hv[e], w.z, a2[e]);
                a3[e] = fmaf(hv[e], w.w, a3[e]);
            }
        }
        __syncthreads();
        float hn[8];
#pragma unroll
        for (int e = 0; e < 8; e++) {
            float iv = sigmf(a0[e]);
            float fv = sigmf(a1[e]);
            float gv = tanhf(a2[e]);
            float ov = sigmf(a3[e]);
            c[e] = fv * c[e] + iv * gv;
            hn[e] = ov * tanhf(c[e]);
        }
        hsm4[j * 2 + 0] = make_float4(hn[0], hn[1], hn[2], hn[3]);
        hsm4[j * 2 + 1] = make_float4(hn[4], hn[5], hn[6], hn[7]);
#pragma unroll
        for (int e = 0; e < 8; e++)
            hout[((size_t)t * E_ + e0 + e) * 64 + j] = hn[e];
        __syncthreads();
    }
}

// ---------------- output projection ----------------
__global__ void out_proj(const float* __restrict__ hf, const float* __restrict__ hr,
                         const float* __restrict__ priW, const float* __restrict__ prib,
                         const float* __restrict__ encW, const float* __restrict__ encb,
                         float* __restrict__ out) {
    int m = blockIdx.x * blockDim.x + threadIdx.x;
    if (m >= TE) return;
    const float* f = hf + (size_t)m * 64;
    const float* r = hr + (size_t)m * 64;
    float p0 = prib[0], p1 = prib[1], e0 = encb[0], e1 = encb[1];
#pragma unroll 8
    for (int k = 0; k < 64; k++) {
        float fv = f[k];
        p0 = fmaf(fv, priW[k], p0);
        p1 = fmaf(fv, priW[64 + k], p1);
        e0 = fmaf(fv, encW[k], e0);
        e1 = fmaf(fv, encW[128 + k], e1);
    }
#pragma unroll 8
    for (int k = 0; k < 64; k++) {
        float rv = r[k];
        e0 = fmaf(rv, encW[64 + k], e0);
        e1 = fmaf(rv, encW[192 + k], e1);
    }
    float4 o = make_float4(p0, p1, e0, e1);
    *(float4*)(out + (size_t)m * 4) = o;
}

// ---------------- host launch ----------------
extern "C" void kernel_launch(void* const* d_in, const int* in_sizes, int n_in,
                              void* d_out, int out_size) {
    const float* x     = (const float*)d_in[0];
    const int* send    = (const int*)d_in[2];
    const int* recv    = (const int*)d_in[3];
    const float* m1W1 = (const float*)d_in[4],  *m1b1 = (const float*)d_in[5];
    const float* m1W2 = (const float*)d_in[6],  *m1b2 = (const float*)d_in[7];
    const float* m2W1 = (const float*)d_in[8],  *m2b1 = (const float*)d_in[9];
    const float* m2W2 = (const float*)d_in[10], *m2b2 = (const float*)d_in[11];
    const float* m3W1 = (const float*)d_in[12], *m3b1 = (const float*)d_in[13];
    const float* m3W2 = (const float*)d_in[14], *m3b2 = (const float*)d_in[15];
    const float* m4W1 = (const float*)d_in[16], *m4b1 = (const float*)d_in[17];
    const float* m4W2 = (const float*)d_in[18], *m4b2 = (const float*)d_in[19];
    const float* fWih = (const float*)d_in[20], *fWhh = (const float*)d_in[21];
    const float* fbih = (const float*)d_in[22], *fbhh = (const float*)d_in[23];
    const float* rWih = (const float*)d_in[24], *rWhh = (const float*)d_in[25];
    const float* rbih = (const float*)d_in[26], *rbhh = (const float*)d_in[27];
    const float* encW = (const float*)d_in[28], *encb = (const float*)d_in[29];
    const float* priW = (const float*)d_in[30], *prib = (const float*)d_in[31];

    __nv_bfloat16 *whi, *wlo, *nbh, *nbl, *h1h, *h1l, *nsh, *nsl, *n3h, *n3l;
    __nv_bfloat16 *tmph, *tmpl, *e2h, *e2l, *e4h, *e4l;
    float *gfp, *grp_, *hfp, *hrp;
    cudaGetSymbolAddress((void**)&whi,  g_whi);
    cudaGetSymbolAddress((void**)&wlo,  g_wlo);
    cudaGetSymbolAddress((void**)&nbh,  g_nbh);
    cudaGetSymbolAddress((void**)&nbl,  g_nbl);
    cudaGetSymbolAddress((void**)&h1h,  g_h1h);
    cudaGetSymbolAddress((void**)&h1l,  g_h1l);
    cudaGetSymbolAddress((void**)&nsh,  g_nsh);
    cudaGetSymbolAddress((void**)&nsl,  g_nsl);
    cudaGetSymbolAddress((void**)&n3h,  g_n3h);
    cudaGetSymbolAddress((void**)&n3l,  g_n3l);
    cudaGetSymbolAddress((void**)&tmph, g_tmph);
    cudaGetSymbolAddress((void**)&tmpl, g_tmpl);
    cudaGetSymbolAddress((void**)&e2h,  g_e2h);
    cudaGetSymbolAddress((void**)&e2l,  g_e2l);
    cudaGetSymbolAddress((void**)&e4h,  g_e4h);
    cudaGetSymbolAddress((void**)&e4l,  g_e4l);
    cudaGetSymbolAddress((void**)&gfp,  g_gf);
    cudaGetSymbolAddress((void**)&grp_, g_gr);
    cudaGetSymbolAddress((void**)&hfp,  g_hf);
    cudaGetSymbolAddress((void**)&hrp,  g_hr);

    cudaFuncSetAttribute(lstm_kernel, cudaFuncAttributeMaxDynamicSharedMemorySize, LSTM_SMEM);
    cudaFuncSetAttribute(gemm_tc<0, 1>, cudaFuncAttributeMaxDynamicSharedMemorySize, GEMM_SMEM);
    cudaFuncSetAttribute(gemm_tc<1, 1>, cudaFuncAttributeMaxDynamicSharedMemorySize, GEMM_SMEM);
    cudaFuncSetAttribute(gemm_tc<2, 1>, cudaFuncAttributeMaxDynamicSharedMemorySize, GEMM_SMEM);
    cudaFuncSetAttribute(gemm_tc<0, 0>, cudaFuncAttributeMaxDynamicSharedMemorySize, GEMM_SMEM);

    build_rlist<<<1, 64>>>(recv);

    // split weights into bf16 hi/lo arena
    splitk<<<256, 256>>>(m1W2, whi + WOFF_M1W2, wlo + WOFF_M1W2, 65536);
    splitk<<<512, 256>>>(m2W1, whi + WOFF_M2W1, wlo + WOFF_M2W1, 131072);
    splitk<<<256, 256>>>(m2W2, whi + WOFF_M2W2, wlo + WOFF_M2W2, 65536);
    splitk<<<256, 256>>>(m3W1, whi + WOFF_M3W1, wlo + WOFF_M3W1, 65536);
    splitk<<<256, 256>>>(m3W2, whi + WOFF_M3W2, wlo + WOFF_M3W2, 65536);
    splitk<<<768, 256>>>(m4W1, whi + WOFF_M4W1, wlo + WOFF_M4W1, 196608);
    splitk<<<256, 256>>>(m4W2, whi + WOFF_M4W2, wlo + WOFF_M4W2, 65536);
    splitk<<<256, 256>>>(fWih, whi + WOFF_FWIH, wlo + WOFF_FWIH, 65536);
    splitk<<<256, 256>>>(rWih, whi + WOFF_RWIH, wlo + WOFF_RWIH, 65536);

    // mlp1
    mlp1_fc1<<<TN * H_ / 256, 256>>>(x, m1W1, m1b1);
    gemm_tc<0, 1><<<TN / 128, 256, GEMM_SMEM>>>(nbh, nbl, whi + WOFF_M1W2, wlo + WOFF_M1W2,
        m1b2, nullptr, nullptr, h1h, h1l, H_, nullptr, nullptr, nullptr, nullptr, nullptr, nullptr);
    // mlp2 (fused node2edge gather)
    gemm_tc<1, 1><<<TE / 128, 256, GEMM_SMEM>>>(nullptr, nullptr, whi + WOFF_M2W1, wlo + WOFF_M2W1,
        m2b1, nullptr, nullptr, tmph, tmpl, 2 * H_, send, recv, h1h, h1l, nullptr, nullptr);
    gemm_tc<0, 1><<<TE / 128, 256, GEMM_SMEM>>>(tmph, tmpl, whi + WOFF_M2W2, wlo + WOFF_M2W2,
        m2b2, nullptr, nullptr, e2h, e2l, H_, nullptr, nullptr, nullptr, nullptr, nullptr, nullptr);
    // edge2node + mlp3
    edge2node<<<TN, 256>>>();
    gemm_tc<0, 1><<<TN / 128, 256, GEMM_SMEM>>>(nsh, nsl, whi + WOFF_M3W1, wlo + WOFF_M3W1,
        m3b1, nullptr, nullptr, nbh, nbl, H_, nullptr, nullptr, nullptr, nullptr, nullptr, nullptr);
    gemm_tc<0, 1><<<TN / 128, 256, GEMM_SMEM>>>(nbh, nbl, whi + WOFF_M3W2, wlo + WOFF_M3W2,
        m3b2, nullptr, nullptr, n3h, n3l, H_, nullptr, nullptr, nullptr, nullptr, nullptr, nullptr);
    // mlp4 (fused gather: n3[send], n3[recv], e2 skip)
    gemm_tc<2, 1><<<TE / 128, 256, GEMM_SMEM>>>(nullptr, nullptr, whi + WOFF_M4W1, wlo + WOFF_M4W1,
        m4b1, nullptr, nullptr, tmph, tmpl, 3 * H_, send, recv, n3h, n3l, e2h, e2l);
    gemm_tc<0, 1><<<TE / 128, 256, GEMM_SMEM>>>(tmph, tmpl, whi + WOFF_M4W2, wlo + WOFF_M4W2,
        m4b2, nullptr, nullptr, e4h, e4l, H_, nullptr, nullptr, nullptr, nullptr, nullptr, nullptr);
    // LSTM input projections (fp32 out, both biases folded)
    gemm_tc<0, 0><<<TE / 128, 256, GEMM_SMEM>>>(e4h, e4l, whi + WOFF_FWIH, wlo + WOFF_FWIH,
        fbih, fbhh, gfp, nullptr, nullptr, H_, nullptr, nullptr, nullptr, nullptr, nullptr, nullptr);
    gemm_tc<0, 0><<<TE / 128, 256, GEMM_SMEM>>>(e4h, e4l, whi + WOFF_RWIH, wlo + WOFF_RWIH,
        rbih, rbhh, grp_, nullptr, nullptr, H_, nullptr, nullptr, nullptr, nullptr, nullptr, nullptr);
    // recurrence
    lstm_kernel<<<2 * LSTM_GROUPS, 64, LSTM_SMEM>>>(gfp, grp_, fWhh, rWhh, hfp, hrp);
    // outputs
    out_proj<<<TE / 256, 256>>>(hfp, hrp, priW, prib, encW, encb, (float*)d_out);
}

// round 7
// speedup vs baseline: 1.1121x; 1.1121x over previous
#include <cuda_runtime.h>
#include <cuda_bf16.h>
#include <cstdint>

// ---------------- problem constants ----------------
constexpr int T_ = 64, N_ = 40, D_ = 4, H_ = 256, R_ = 64;
constexpr int E_ = N_ * (N_ - 1);        // 1560
constexpr int TE = T_ * E_;              // 99840
constexpr int TN = T_ * N_;              // 2560

// ---------------- scratch ----------------
__device__ __align__(16) __nv_bfloat16 g_nbh[TN * H_], g_nbl[TN * H_];
__device__ __align__(16) __nv_bfloat16 g_h1h[TN * H_], g_h1l[TN * H_];
__device__ __align__(16) __nv_bfloat16 g_nsh[TN * H_], g_nsl[TN * H_];
__device__ __align__(16) __nv_bfloat16 g_n3h[TN * H_], g_n3l[TN * H_];
__device__ __align__(16) __nv_bfloat16 g_tmph[TE * H_], g_tmpl[TE * H_];
__device__ __align__(16) __nv_bfloat16 g_e2h[TE * H_], g_e2l[TE * H_];
__device__ __align__(16) __nv_bfloat16 g_e4h[TE * H_], g_e4l[TE * H_];
constexpr int WOFF_M1W2 = 0;
constexpr int WOFF_M2W1 = 65536;
constexpr int WOFF_M2W2 = 196608;
constexpr int WOFF_M3W1 = 262144;
constexpr int WOFF_M3W2 = 327680;
constexpr int WOFF_M4W1 = 393216;
constexpr int WOFF_M4W2 = 589824;
constexpr int WOFF_FWIH = 655360;
constexpr int WOFF_RWIH = 720896;
constexpr int WTOTAL    = 786432;
__device__ __align__(16) __nv_bfloat16 g_whi[WTOTAL], g_wlo[WTOTAL];
__device__ float g_gf[TE * H_];
__device__ float g_gr[TE * H_];
__device__ float g_hf[TE * R_];
__device__ float g_hr[TE * R_];
__device__ int   g_rlist[N_ * (N_ - 1)];

__device__ __forceinline__ float eluf(float v) { return v > 0.f ? v : expm1f(v); }
__device__ __forceinline__ float sigmf(float v) { return 1.f / (1.f + expf(-v)); }

__device__ __forceinline__ void bsplit2(float x0, float x1, uint32_t& hi, uint32_t& lo) {
    asm("cvt.rn.bf16x2.f32 %0, %1, %2;" : "=r"(hi) : "f"(x1), "f"(x0));
    __nv_bfloat162 h = *reinterpret_cast<__nv_bfloat162*>(&hi);
    float r0 = x0 - __bfloat162float(h.x);
    float r1 = x1 - __bfloat162float(h.y);
    asm("cvt.rn.bf16x2.f32 %0, %1, %2;" : "=r"(lo) : "f"(r1), "f"(r0));
}

__device__ __forceinline__ void mma_bf16(float* d, const uint32_t* a, const uint32_t* b) {
    asm volatile(
        "mma.sync.aligned.m16n8k16.row.col.f32.bf16.bf16.f32 "
        "{%0,%1,%2,%3},{%4,%5,%6,%7},{%8,%9},{%0,%1,%2,%3};"
        : "+f"(d[0]), "+f"(d[1]), "+f"(d[2]), "+f"(d[3])
        : "r"(a[0]), "r"(a[1]), "r"(a[2]), "r"(a[3]), "r"(b[0]), "r"(b[1]));
}

// ---------------- weight split (once per launch, tiny) ----------------
__global__ void splitk(const float* __restrict__ in, __nv_bfloat16* __restrict__ oh,
                       __nv_bfloat16* __restrict__ ol, int n) {
    int i = blockIdx.x * blockDim.x + threadIdx.x;
    if (i >= n) return;
    float v = in[i];
    __nv_bfloat16 h = __float2bfloat16(v);
    oh[i] = h;
    ol[i] = __float2bfloat16(v - __bfloat162float(h));
}

// ---------------- mlp1 fc1 (K=4, tiny) -> split out ----------------
__global__ void mlp1_fc1(const float* __restrict__ x, const float* __restrict__ W1,
                         const float* __restrict__ b1) {
    int idx = blockIdx.x * blockDim.x + threadIdx.x;
    int row = idx >> 8;
    int j = idx & 255;
    const float* xr = x + row * D_;
    const float* w = W1 + j * D_;
    float v = b1[j] + xr[0] * w[0] + xr[1] * w[1] + xr[2] * w[2] + xr[3] * w[3];
    v = eluf(v);
    __nv_bfloat16 h = __float2bfloat16(v);
    g_nbh[idx] = h;
    g_nbl[idx] = __float2bfloat16(v - __bfloat162float(h));
}

// ---------------- build per-node incoming edge lists ----------------
__global__ void build_rlist(const int* __restrict__ recv) {
    int n = threadIdx.x;
    if (n >= N_) return;
    int p = 0;
    for (int e = 0; e < E_; e++)
        if (recv[e] == n) g_rlist[n * (N_ - 1) + p++] = e;
}

// ---------------- edge2node scatter-add (split in, split out) ----------------
__global__ void edge2node() {
    int b = blockIdx.x;
    int t = b / N_;
    int n = b - t * N_;
    int c = threadIdx.x;
    const int* lst = g_rlist + n * (N_ - 1);
    float s = 0.f;
#pragma unroll 13
    for (int i = 0; i < N_ - 1; i++) {
        int e = lst[i];
        size_t idx = ((size_t)t * E_ + e) * H_ + c;
        s += __bfloat162float(g_e2h[idx]) + __bfloat162float(g_e2l[idx]);
    }
    __nv_bfloat16 h = __float2bfloat16(s);
    g_nsh[(size_t)b * H_ + c] = h;
    g_nsl[(size_t)b * H_ + c] = __float2bfloat16(s - __bfloat162float(h));
}

// ------- bf16x3 tensor-core GEMM: round-3 structure, pre-split inputs, reordered passes -------
// Block tile 128x128, 8 warps of 64x32, k-chunk 16 elems. 2 CTAs/SM.
// smem rows: 8 bf16x2 words + 1 pad word (stride 9) — conflict-free fragment LDS (verified R3).
// MODE 0: plain A; MODE 1: gather send|recv (Kd=512); MODE 2: send|recv|skip (Kd=768)
// OUT 0: fp32 + bias + bias2 (LSTM gates). OUT 1: ELU + split bf16 out.
constexpr int SMSB = 9;

template <int MODE, int OUT>
__global__ __launch_bounds__(256, 2) void gemm_tc(
    const __nv_bfloat16* __restrict__ Ah, const __nv_bfloat16* __restrict__ Al,
    const __nv_bfloat16* __restrict__ Wh, const __nv_bfloat16* __restrict__ Wl,
    const float* __restrict__ bias, const float* __restrict__ bias2,
    float* __restrict__ Cf, __nv_bfloat16* __restrict__ Ch, __nv_bfloat16* __restrict__ Cl,
    int Kd,
    const int* __restrict__ send, const int* __restrict__ recv,
    const __nv_bfloat16* __restrict__ s0h, const __nv_bfloat16* __restrict__ s0l,
    const __nv_bfloat16* __restrict__ s1h, const __nv_bfloat16* __restrict__ s1l) {
    __shared__ uint32_t sAhi[128 * SMSB], sAlo[128 * SMSB];
    __shared__ uint32_t sWhi[128 * SMSB], sWlo[128 * SMSB];

    const int tid = threadIdx.x;
    const int bm = blockIdx.y * 128;
    const int bn = blockIdx.x * 128;
    const int lr = tid >> 1;            // row within tile
    const int kw = (tid & 1) * 4;       // word offset (elem offset = kw*2)

    // ---- A row pointers (fused gather) ----
    const __nv_bfloat16 *arh = nullptr, *arl = nullptr;
    const __nv_bfloat16 *a1h = nullptr, *a1l = nullptr, *a2h = nullptr, *a2l = nullptr;
    {
        int m = bm + lr;
        if (MODE == 0) {
            arh = Ah + (size_t)m * Kd;
            arl = Al + (size_t)m * Kd;
        } else {
            int t = m / E_;
            int e = m - t * E_;
            size_t so = ((size_t)t * N_ + send[e]) * H_;
            size_t ro = ((size_t)t * N_ + recv[e]) * H_;
            arh = s0h + so; arl = s0l + so;
            a1h = s0h + ro; a1l = s0l + ro;
            if (MODE == 2) { a2h = s1h + (size_t)m * H_; a2l = s1l + (size_t)m * H_; }
        }
    }
    const __nv_bfloat16* wrh = Wh + (size_t)(bn + lr) * Kd;
    const __nv_bfloat16* wrl = Wl + (size_t)(bn + lr) * Kd;

    const int warp = tid >> 5, lane = tid & 31;
    const int wm = (warp >> 2) * 64;    // 0 / 64
    const int wn = (warp & 3) * 32;     // 0 / 32 / 64 / 96
    const int grp = lane >> 2, q = lane & 3;

    float acc[4][4][4] = {};

    uint4 vah, val, vwh, vwl;
    auto load_g = [&](int kt) {       // kt = chunk base in elems
        int ke = kt + kw * 2;
        const __nv_bfloat16 *ph, *pl;
        if (MODE == 0) {
            ph = arh + ke; pl = arl + ke;
        } else {
            int off = ke & 255;
            if (MODE == 1) {
                ph = (ke < 256 ? arh : a1h) + off;
                pl = (ke < 256 ? arl : a1l) + off;
            } else {
                ph = (ke < 256 ? arh : (ke < 512 ? a1h : a2h)) + off;
                pl = (ke < 256 ? arl : (ke < 512 ? a1l : a2l)) + off;
            }
        }
        vah = *(const uint4*)ph;
        val = *(const uint4*)pl;
        vwh = *(const uint4*)(wrh + ke);
        vwl = *(const uint4*)(wrl + ke);
    };

    load_g(0);

    const int nsteps = Kd >> 4;
    for (int step = 0; step < nsteps; step++) {
        __syncthreads();   // previous iteration's fragment LDS complete
        {
            uint32_t* p = &sAhi[lr * SMSB + kw];
            p[0] = vah.x; p[1] = vah.y; p[2] = vah.z; p[3] = vah.w;
            p = &sAlo[lr * SMSB + kw];
            p[0] = val.x; p[1] = val.y; p[2] = val.z; p[3] = val.w;
            p = &sWhi[lr * SMSB + kw];
            p[0] = vwh.x; p[1] = vwh.y; p[2] = vwh.z; p[3] = vwh.w;
            p = &sWlo[lr * SMSB + kw];
            p[0] = vwl.x; p[1] = vwl.y; p[2] = vwl.z; p[3] = vwl.w;
        }
        __syncthreads();

        if (step + 1 < nsteps) load_g((step + 1) << 4);

        // B fragments for all 4 n-tiles
        uint32_t bh[4][2], bl[4][2];
#pragma unroll
        for (int nf = 0; nf < 4; nf++) {
            int c = (wn + nf * 8 + grp) * SMSB + q;
            bh[nf][0] = sWhi[c]; bh[nf][1] = sWhi[c + 4];
            bl[nf][0] = sWlo[c]; bl[nf][1] = sWlo[c + 4];
        }
#pragma unroll
        for (int mf = 0; mf < 4; mf++) {
            int r0 = (wm + mf * 16 + grp) * SMSB + q;
            int r1 = r0 + 8 * SMSB;
            uint32_t ah[4] = {sAhi[r0], sAhi[r1], sAhi[r0 + 4], sAhi[r1 + 4]};
            uint32_t al[4] = {sAlo[r0], sAlo[r1], sAlo[r0 + 4], sAlo[r1 + 4]};
            // pass-reordered: same acc touched at distance 4 (breaks RAW chains)
#pragma unroll
            for (int nf = 0; nf < 4; nf++) mma_bf16(acc[mf][nf], ah, bh[nf]);
#pragma unroll
            for (int nf = 0; nf < 4; nf++) mma_bf16(acc[mf][nf], ah, bl[nf]);
#pragma unroll
            for (int nf = 0; nf < 4; nf++) mma_bf16(acc[mf][nf], al, bh[nf]);
        }
    }

    // ---- epilogue ----
#pragma unroll
    for (int mf = 0; mf < 4; mf++) {
        int r0 = bm + wm + mf * 16 + grp;
        int r1 = r0 + 8;
#pragma unroll
        for (int nf = 0; nf < 4; nf++) {
            int col = bn + wn + nf * 8 + 2 * q;
            float b0 = bias[col], b1 = bias[col + 1];
            if (OUT == 0) { b0 += bias2[col]; b1 += bias2[col + 1]; }
            float x0 = acc[mf][nf][0] + b0;
            float x1 = acc[mf][nf][1] + b1;
            float x2 = acc[mf][nf][2] + b0;
            float x3 = acc[mf][nf][3] + b1;
            if (OUT == 1) {
                x0 = eluf(x0); x1 = eluf(x1); x2 = eluf(x2); x3 = eluf(x3);
                uint32_t h01, l01, h23, l23;
                bsplit2(x0, x1, h01, l01);
                bsplit2(x2, x3, h23, l23);
                *(uint32_t*)(Ch + (size_t)r0 * 256 + col) = h01;
                *(uint32_t*)(Cl + (size_t)r0 * 256 + col) = l01;
                *(uint32_t*)(Ch + (size_t)r1 * 256 + col) = h23;
                *(uint32_t*)(Cl + (size_t)r1 * 256 + col) = l23;
            } else {
                *(float2*)(Cf + (size_t)r0 * 256 + col) = make_float2(x0, x1);
                *(float2*)(Cf + (size_t)r1 * 256 + col) = make_float2(x2, x3);
            }
        }
    }
}

// ---------------- fused bidirectional LSTM (recurrence only) ----------------
constexpr int LSTM_GROUPS = E_ / 8;
constexpr int LSTM_SMEM = 64 * 256 * 4 + 64 * 8 * 4;

__global__ __launch_bounds__(64) void lstm_kernel(
    const float* __restrict__ gf, const float* __restrict__ gr,
    const float* __restrict__ fWhh, const float* __restrict__ rWhh,
    float* __restrict__ hfOut, float* __restrict__ hrOut) {
    extern __shared__ float sm[];
    float* Wq = sm;
    float4* hsm4 = (float4*)(sm + 64 * 256);

    int dir; int grp;
    const float* gates; const float* Whh; float* hout;
    if (blockIdx.x < LSTM_GROUPS) {
        dir = 0; grp = blockIdx.x; gates = gf; Whh = fWhh; hout = hfOut;
    } else {
        dir = 1; grp = blockIdx.x - LSTM_GROUPS; gates = gr; Whh = rWhh; hout = hrOut;
    }
    const int j = threadIdx.x;

    for (int idx = j; idx < 64 * 256; idx += 64) {
        int k = idx >> 8;
        int rem = idx & 255;
        int jj = rem >> 2;
        int q = rem & 3;
        Wq[idx] = Whh[(q * 64 + jj) * 64 + k];
    }
    for (int i = j; i < 128; i += 64) hsm4[i] = make_float4(0.f, 0.f, 0.f, 0.f);

    const int e0 = grp * 8;
    float c[8];
#pragma unroll
    for (int e = 0; e < 8; e++) c[e] = 0.f;
    __syncthreads();

    for (int s = 0; s < T_; s++) {
        int t = dir ? (T_ - 1 - s) : s;
        float a0[8], a1[8], a2[8], a3[8];
#pragma unroll
        for (int e = 0; e < 8; e++) {
            const float* gp = gates + ((size_t)t * E_ + e0 + e) * 256;
            a0[e] = gp[j]; a1[e] = gp[64 + j]; a2[e] = gp[128 + j]; a3[e] = gp[192 + j];
        }
#pragma unroll 16
        for (int k = 0; k < 64; k++) {
            float4 w  = *(const float4*)&Wq[k * 256 + j * 4];
            float4 hA = hsm4[k * 2 + 0];
            float4 hB = hsm4[k * 2 + 1];
            float hv[8] = {hA.x, hA.y, hA.z, hA.w, hB.x, hB.y, hB.z, hB.w};
#pragma unroll
            for (int e = 0; e < 8; e++) {
                a0[e] = fmaf(hv[e], w.x, a0[e]);
                a1[e] = fmaf(hv[e], w.y, a1[e]);
                a2[e] = fmaf(hv[e], w.z, a2[e]);
                a3[e] = fmaf(hv[e], w.w, a3[e]);
            }
        }
        __syncthreads();
        float hn[8];
#pragma unroll
        for (int e = 0; e < 8; e++) {
            float iv = sigmf(a0[e]);
            float fv = sigmf(a1[e]);
            float gv = tanhf(a2[e]);
            float ov = sigmf(a3[e]);
            c[e] = fv * c[e] + iv * gv;
            hn[e] = ov * tanhf(c[e]);
        }
        hsm4[j * 2 + 0] = make_float4(hn[0], hn[1], hn[2], hn[3]);
        hsm4[j * 2 + 1] = make_float4(hn[4], hn[5], hn[6], hn[7]);
#pragma unroll
        for (int e = 0; e < 8; e++)
            hout[((size_t)t * E_ + e0 + e) * 64 + j] = hn[e];
        __syncthreads();
    }
}

// ---------------- output projection ----------------
__global__ void out_proj(const float* __restrict__ hf, const float* __restrict__ hr,
                         const float* __restrict__ priW, const float* __restrict__ prib,
                         const float* __restrict__ encW, const float* __restrict__ encb,
                         float* __restrict__ out) {
    int m = blockIdx.x * blockDim.x + threadIdx.x;
    if (m >= TE) return;
    const float* f = hf + (size_t)m * 64;
    const float* r = hr + (size_t)m * 64;
    float p0 = prib[0], p1 = prib[1], e0 = encb[0], e1 = encb[1];
#pragma unroll 8
    for (int k = 0; k < 64; k++) {
        float fv = f[k];
        p0 = fmaf(fv, priW[k], p0);
        p1 = fmaf(fv, priW[64 + k], p1);
        e0 = fmaf(fv, encW[k], e0);
        e1 = fmaf(fv, encW[128 + k], e1);
    }
#pragma unroll 8
    for (int k = 0; k < 64; k++) {
        float rv = r[k];
        e0 = fmaf(rv, encW[64 + k], e0);
        e1 = fmaf(rv, encW[192 + k], e1);
    }
    float4 o = make_float4(p0, p1, e0, e1);
    *(float4*)(out + (size_t)m * 4) = o;
}

// ---------------- host launch ----------------
extern "C" void kernel_launch(void* const* d_in, const int* in_sizes, int n_in,
                              void* d_out, int out_size) {
    const float* x     = (const float*)d_in[0];
    const int* send    = (const int*)d_in[2];
    const int* recv    = (const int*)d_in[3];
    const float* m1W1 = (const float*)d_in[4],  *m1b1 = (const float*)d_in[5];
    const float* m1W2 = (const float*)d_in[6],  *m1b2 = (const float*)d_in[7];
    const float* m2W1 = (const float*)d_in[8],  *m2b1 = (const float*)d_in[9];
    const float* m2W2 = (const float*)d_in[10], *m2b2 = (const float*)d_in[11];
    const float* m3W1 = (const float*)d_in[12], *m3b1 = (const float*)d_in[13];
    const float* m3W2 = (const float*)d_in[14], *m3b2 = (const float*)d_in[15];
    const float* m4W1 = (const float*)d_in[16], *m4b1 = (const float*)d_in[17];
    const float* m4W2 = (const float*)d_in[18], *m4b2 = (const float*)d_in[19];
    const float* fWih = (const float*)d_in[20], *fWhh = (const float*)d_in[21];
    const float* fbih = (const float*)d_in[22], *fbhh = (const float*)d_in[23];
    const float* rWih = (const float*)d_in[24], *rWhh = (const float*)d_in[25];
    const float* rbih = (const float*)d_in[26], *rbhh = (const float*)d_in[27];
    const float* encW = (const float*)d_in[28], *encb = (const float*)d_in[29];
    const float* priW = (const float*)d_in[30], *prib = (const float*)d_in[31];

    __nv_bfloat16 *whi, *wlo, *nbh, *nbl, *h1h, *h1l, *nsh, *nsl, *n3h, *n3l;
    __nv_bfloat16 *tmph, *tmpl, *e2h, *e2l, *e4h, *e4l;
    float *gfp, *grp_, *hfp, *hrp;
    cudaGetSymbolAddress((void**)&whi,  g_whi);
    cudaGetSymbolAddress((void**)&wlo,  g_wlo);
    cudaGetSymbolAddress((void**)&nbh,  g_nbh);
    cudaGetSymbolAddress((void**)&nbl,  g_nbl);
    cudaGetSymbolAddress((void**)&h1h,  g_h1h);
    cudaGetSymbolAddress((void**)&h1l,  g_h1l);
    cudaGetSymbolAddress((void**)&nsh,  g_nsh);
    cudaGetSymbolAddress((void**)&nsl,  g_nsl);
    cudaGetSymbolAddress((void**)&n3h,  g_n3h);
    cudaGetSymbolAddress((void**)&n3l,  g_n3l);
    cudaGetSymbolAddress((void**)&tmph, g_tmph);
    cudaGetSymbolAddress((void**)&tmpl, g_tmpl);
    cudaGetSymbolAddress((void**)&e2h,  g_e2h);
    cudaGetSymbolAddress((void**)&e2l,  g_e2l);
    cudaGetSymbolAddress((void**)&e4h,  g_e4h);
    cudaGetSymbolAddress((void**)&e4l,  g_e4l);
    cudaGetSymbolAddress((void**)&gfp,  g_gf);
    cudaGetSymbolAddress((void**)&grp_, g_gr);
    cudaGetSymbolAddress((void**)&hfp,  g_hf);
    cudaGetSymbolAddress((void**)&hrp,  g_hr);

    cudaFuncSetAttribute(lstm_kernel, cudaFuncAttributeMaxDynamicSharedMemorySize, LSTM_SMEM);

    build_rlist<<<1, 64>>>(recv);

    // split weights into bf16 hi/lo arena
    splitk<<<256, 256>>>(m1W2, whi + WOFF_M1W2, wlo + WOFF_M1W2, 65536);
    splitk<<<512, 256>>>(m2W1, whi + WOFF_M2W1, wlo + WOFF_M2W1, 131072);
    splitk<<<256, 256>>>(m2W2, whi + WOFF_M2W2, wlo + WOFF_M2W2, 65536);
    splitk<<<256, 256>>>(m3W1, whi + WOFF_M3W1, wlo + WOFF_M3W1, 65536);
    splitk<<<256, 256>>>(m3W2, whi + WOFF_M3W2, wlo + WOFF_M3W2, 65536);
    splitk<<<768, 256>>>(m4W1, whi + WOFF_M4W1, wlo + WOFF_M4W1, 196608);
    splitk<<<256, 256>>>(m4W2, whi + WOFF_M4W2, wlo + WOFF_M4W2, 65536);
    splitk<<<256, 256>>>(fWih, whi + WOFF_FWIH, wlo + WOFF_FWIH, 65536);
    splitk<<<256, 256>>>(rWih, whi + WOFF_RWIH, wlo + WOFF_RWIH, 65536);

    // mlp1
    mlp1_fc1<<<TN * H_ / 256, 256>>>(x, m1W1, m1b1);
    gemm_tc<0, 1><<<dim3(2, TN / 128), 256>>>(nbh, nbl, whi + WOFF_M1W2, wlo + WOFF_M1W2,
        m1b2, nullptr, nullptr, h1h, h1l, H_, nullptr, nullptr, nullptr, nullptr, nullptr, nullptr);
    // mlp2 (fused node2edge gather)
    gemm_tc<1, 1><<<dim3(2, TE / 128), 256>>>(nullptr, nullptr, whi + WOFF_M2W1, wlo + WOFF_M2W1,
        m2b1, nullptr, nullptr, tmph, tmpl, 2 * H_, send, recv, h1h, h1l, nullptr, nullptr);
    gemm_tc<0, 1><<<dim3(2, TE / 128), 256>>>(tmph, tmpl, whi + WOFF_M2W2, wlo + WOFF_M2W2,
        m2b2, nullptr, nullptr, e2h, e2l, H_, nullptr, nullptr, nullptr, nullptr, nullptr, nullptr);
    // edge2node + mlp3
    edge2node<<<TN, 256>>>();
    gemm_tc<0, 1><<<dim3(2, TN / 128), 256>>>(nsh, nsl, whi + WOFF_M3W1, wlo + WOFF_M3W1,
        m3b1, nullptr, nullptr, nbh, nbl, H_, nullptr, nullptr, nullptr, nullptr, nullptr, nullptr);
    gemm_tc<0, 1><<<dim3(2, TN / 128), 256>>>(nbh, nbl, whi + WOFF_M3W2, wlo + WOFF_M3W2,
        m3b2, nullptr, nullptr, n3h, n3l, H_, nullptr, nullptr, nullptr, nullptr, nullptr, nullptr);
    // mlp4 (fused gather: n3[send], n3[recv], e2 skip)
    gemm_tc<2, 1><<<dim3(2, TE / 128), 256>>>(nullptr, nullptr, whi + WOFF_M4W1, wlo + WOFF_M4W1,
        m4b1, nullptr, nullptr, tmph, tmpl, 3 * H_, send, recv, n3h, n3l, e2h, e2l);
    gemm_tc<0, 1><<<dim3(2, TE / 128), 256>>>(tmph, tmpl, whi + WOFF_M4W2, wlo + WOFF_M4W2,
        m4b2, nullptr, nullptr, e4h, e4l, H_, nullptr, nullptr, nullptr, nullptr, nullptr, nullptr);
    // LSTM input projections (fp32 out, both biases folded)
    gemm_tc<0, 0><<<dim3(2, TE / 128), 256>>>(e4h, e4l, whi + WOFF_FWIH, wlo + WOFF_FWIH,
        fbih, fbhh, gfp, nullptr, nullptr, H_, nullptr, nullptr, nullptr, nullptr, nullptr, nullptr);
    gemm_tc<0, 0><<<dim3(2, TE / 128), 256>>>(e4h, e4l, whi + WOFF_RWIH, wlo + WOFF_RWIH,
        rbih, rbhh, grp_, nullptr, nullptr, H_, nullptr, nullptr, nullptr, nullptr, nullptr, nullptr);
    // recurrence
    lstm_kernel<<<2 * LSTM_GROUPS, 64, LSTM_SMEM>>>(gfp, grp_, fWhh, rWhh, hfp, hrp);
    // outputs
    out_proj<<<TE / 256, 256>>>(hfp, hrp, priW, prib, encW, encb, (float*)d_out);
}

// round 8
// speedup vs baseline: 1.3850x; 1.2454x over previous
#include <cuda_runtime.h>
#include <cuda_bf16.h>
#include <cstdint>

// ---------------- problem constants ----------------
constexpr int T_ = 64, N_ = 40, D_ = 4, H_ = 256, R_ = 64;
constexpr int E_ = N_ * (N_ - 1);        // 1560
constexpr int TE = T_ * E_;              // 99840
constexpr int TN = T_ * N_;              // 2560

// ---------------- scratch ----------------
__device__ __align__(16) __nv_bfloat16 g_nbh[TN * H_], g_nbl[TN * H_];
__device__ __align__(16) __nv_bfloat16 g_h1h[TN * H_], g_h1l[TN * H_];
__device__ __align__(16) __nv_bfloat16 g_nsh[TN * H_], g_nsl[TN * H_];
__device__ __align__(16) __nv_bfloat16 g_n3h[TN * H_], g_n3l[TN * H_];
__device__ __align__(16) __nv_bfloat16 g_tmph[TE * H_], g_tmpl[TE * H_];
__device__ __align__(16) __nv_bfloat16 g_e2h[TE * H_], g_e2l[TE * H_];
__device__ __align__(16) __nv_bfloat16 g_e4h[TE * H_], g_e4l[TE * H_];
// node-level fp32 partial products
__device__ __align__(16) float g_Ps[TN * H_], g_Pr[TN * H_];
__device__ __align__(16) float g_Qs[TN * H_], g_Qr[TN * H_];
// split weight arena: 12 segments of 65536 (each 256 rows x 256 k)
constexpr int NSEG = 12;
constexpr int SEGSZ = 65536;
__device__ __align__(16) __nv_bfloat16 g_whi[NSEG * SEGSZ], g_wlo[NSEG * SEGSZ];
__device__ float g_gf[TE * H_];
__device__ float g_gr[TE * H_];
__device__ float g_hf[TE * R_];
__device__ float g_hr[TE * R_];
__device__ int   g_rlist[N_ * (N_ - 1)];

__device__ __forceinline__ float eluf(float v) { return v > 0.f ? v : expm1f(v); }
__device__ __forceinline__ float sigmf(float v) { return 1.f / (1.f + expf(-v)); }

__device__ __forceinline__ void bsplit2(float x0, float x1, uint32_t& hi, uint32_t& lo) {
    asm("cvt.rn.bf16x2.f32 %0, %1, %2;" : "=r"(hi) : "f"(x1), "f"(x0));
    __nv_bfloat162 h = *reinterpret_cast<__nv_bfloat162*>(&hi);
    float r0 = x0 - __bfloat162float(h.x);
    float r1 = x1 - __bfloat162float(h.y);
    asm("cvt.rn.bf16x2.f32 %0, %1, %2;" : "=r"(lo) : "f"(r1), "f"(r0));
}

__device__ __forceinline__ void mma_bf16(float* d, const uint32_t* a, const uint32_t* b) {
    asm volatile(
        "mma.sync.aligned.m16n8k16.row.col.f32.bf16.bf16.f32 "
        "{%0,%1,%2,%3},{%4,%5,%6,%7},{%8,%9},{%0,%1,%2,%3};"
        : "+f"(d[0]), "+f"(d[1]), "+f"(d[2]), "+f"(d[3])
        : "r"(a[0]), "r"(a[1]), "r"(a[2]), "r"(a[3]), "r"(b[0]), "r"(b[1]));
}

// ---------------- fused weight split: 12 segments in one launch ----------------
struct SplitSeg { const float* src; int stride; int coff; };
struct SplitArgs { SplitSeg s[NSEG]; };

__global__ void split_all(SplitArgs a, __nv_bfloat16* __restrict__ oh,
                          __nv_bfloat16* __restrict__ ol) {
    int seg = blockIdx.y;
    int idx = blockIdx.x * 256 + threadIdx.x;    // 0..65535
    int j = idx >> 8, k = idx & 255;
    const SplitSeg s = a.s[seg];
    float v = s.src[j * s.stride + s.coff + k];
    __nv_bfloat16 h = __float2bfloat16(v);
    int o = seg * SEGSZ + idx;
    oh[o] = h;
    ol[o] = __float2bfloat16(v - __bfloat162float(h));
}

// ---------------- mlp1 fc1 (K=4, tiny) -> split out ----------------
__global__ void mlp1_fc1(const float* __restrict__ x, const float* __restrict__ W1,
                         const float* __restrict__ b1) {
    int idx = blockIdx.x * blockDim.x + threadIdx.x;
    int row = idx >> 8;
    int j = idx & 255;
    const float* xr = x + row * D_;
    const float* w = W1 + j * D_;
    float v = b1[j] + xr[0] * w[0] + xr[1] * w[1] + xr[2] * w[2] + xr[3] * w[3];
    v = eluf(v);
    __nv_bfloat16 h = __float2bfloat16(v);
    g_nbh[idx] = h;
    g_nbl[idx] = __float2bfloat16(v - __bfloat162float(h));
}

// ---------------- build per-node incoming edge lists ----------------
__global__ void build_rlist(const int* __restrict__ recv) {
    int n = threadIdx.x;
    if (n >= N_) return;
    int p = 0;
    for (int e = 0; e < E_; e++)
        if (recv[e] == n) g_rlist[n * (N_ - 1) + p++] = e;
}

// ---------------- edge2node scatter-add (split in, split out) ----------------
__global__ void edge2node() {
    int b = blockIdx.x;
    int t = b / N_;
    int n = b - t * N_;
    int c = threadIdx.x;
    const int* lst = g_rlist + n * (N_ - 1);
    float s = 0.f;
#pragma unroll 13
    for (int i = 0; i < N_ - 1; i++) {
        int e = lst[i];
        size_t idx = ((size_t)t * E_ + e) * H_ + c;
        s += __bfloat162float(g_e2h[idx]) + __bfloat162float(g_e2l[idx]);
    }
    __nv_bfloat16 h = __float2bfloat16(s);
    g_nsh[(size_t)b * H_ + c] = h;
    g_nsl[(size_t)b * H_ + c] = __float2bfloat16(s - __bfloat162float(h));
}

// ---------------- mlp2-fc1 as node-level products + gather-add combine ----------------
// out = elu(Ps[send] + Pr[recv]) with m2b1 pre-folded into Ps
__global__ void combine2(const float* __restrict__ Ps, const float* __restrict__ Pr,
                         __nv_bfloat16* __restrict__ oh, __nv_bfloat16* __restrict__ ol,
                         const int* __restrict__ send, const int* __restrict__ recv) {
    int m = blockIdx.x;          // 0..TE-1
    int c = threadIdx.x;         // 0..255
    int t = m / E_;
    int e = m - t * E_;
    size_t bs = ((size_t)t * N_ + send[e]) * H_ + c;
    size_t br = ((size_t)t * N_ + recv[e]) * H_ + c;
    float v = eluf(Ps[bs] + Pr[br]);
    __nv_bfloat16 h = __float2bfloat16(v);
    oh[(size_t)m * H_ + c] = h;
    ol[(size_t)m * H_ + c] = __float2bfloat16(v - __bfloat162float(h));
}

// ------- bf16x3 tensor-core GEMM (round-3 mainloop, pre-split bf16 inputs, K=256) -------
// Block tile 128x128, 8 warps of 64x32, k-chunk 16 elems, 2 CTAs/SM.
// EPI 0: fp32 out, + bias (+bias2) (nullable). EPI 1: ELU + split bf16 out.
// EPI 2: + bias + Qs[send]+Qr[recv] gather, ELU, split bf16 out (mlp4 skip fusion).
constexpr int SMSB = 9;

template <int EPI>
__global__ __launch_bounds__(256, 2) void gemm_tc(
    const __nv_bfloat16* __restrict__ Ah, const __nv_bfloat16* __restrict__ Al,
    const __nv_bfloat16* __restrict__ Wh, const __nv_bfloat16* __restrict__ Wl,
    const float* __restrict__ bias, const float* __restrict__ bias2,
    float* __restrict__ Cf, __nv_bfloat16* __restrict__ Ch, __nv_bfloat16* __restrict__ Cl,
    const int* __restrict__ send, const int* __restrict__ recv,
    const float* __restrict__ Qs, const float* __restrict__ Qr) {
    __shared__ uint32_t sAhi[128 * SMSB], sAlo[128 * SMSB];
    __shared__ uint32_t sWhi[128 * SMSB], sWlo[128 * SMSB];

    const int tid = threadIdx.x;
    const int bm = blockIdx.y * 128;
    const int bn = blockIdx.x * 128;
    const int lr = tid >> 1;            // row within tile
    const int kw = (tid & 1) * 4;       // word offset (elem offset = kw*2)

    const __nv_bfloat16* arh = Ah + (size_t)(bm + lr) * H_;
    const __nv_bfloat16* arl = Al + (size_t)(bm + lr) * H_;
    const __nv_bfloat16* wrh = Wh + (size_t)(bn + lr) * H_;
    const __nv_bfloat16* wrl = Wl + (size_t)(bn + lr) * H_;

    const int warp = tid >> 5, lane = tid & 31;
    const int wm = (warp >> 2) * 64;    // 0 / 64
    const int wn = (warp & 3) * 32;     // 0 / 32 / 64 / 96
    const int grp = lane >> 2, q = lane & 3;

    float acc[4][4][4] = {};

    uint4 vah, val, vwh, vwl;
    auto load_g = [&](int kt) {
        int ke = kt + kw * 2;
        vah = *(const uint4*)(arh + ke);
        val = *(const uint4*)(arl + ke);
        vwh = *(const uint4*)(wrh + ke);
        vwl = *(const uint4*)(wrl + ke);
    };

    load_g(0);

    constexpr int NSTEPS = H_ >> 4;     // 16
#pragma unroll 1
    for (int step = 0; step < NSTEPS; step++) {
        __syncthreads();
        {
            uint32_t* p = &sAhi[lr * SMSB + kw];
            p[0] = vah.x; p[1] = vah.y; p[2] = vah.z; p[3] = vah.w;
            p = &sAlo[lr * SMSB + kw];
            p[0] = val.x; p[1] = val.y; p[2] = val.z; p[3] = val.w;
            p = &sWhi[lr * SMSB + kw];
            p[0] = vwh.x; p[1] = vwh.y; p[2] = vwh.z; p[3] = vwh.w;
            p = &sWlo[lr * SMSB + kw];
            p[0] = vwl.x; p[1] = vwl.y; p[2] = vwl.z; p[3] = vwl.w;
        }
        __syncthreads();

        if (step + 1 < NSTEPS) load_g((step + 1) << 4);

        uint32_t bh[4][2], bl[4][2];
#pragma unroll
        for (int nf = 0; nf < 4; nf++) {
            int c = (wn + nf * 8 + grp) * SMSB + q;
            bh[nf][0] = sWhi[c]; bh[nf][1] = sWhi[c + 4];
            bl[nf][0] = sWlo[c]; bl[nf][1] = sWlo[c + 4];
        }
#pragma unroll
        for (int mf = 0; mf < 4; mf++) {
            int r0 = (wm + mf * 16 + grp) * SMSB + q;
            int r1 = r0 + 8 * SMSB;
            uint32_t ah[4] = {sAhi[r0], sAhi[r1], sAhi[r0 + 4], sAhi[r1 + 4]};
            uint32_t al[4] = {sAlo[r0], sAlo[r1], sAlo[r0 + 4], sAlo[r1 + 4]};
#pragma unroll
            for (int nf = 0; nf < 4; nf++) {
                mma_bf16(acc[mf][nf], ah, bh[nf]);   // hi*hi
                mma_bf16(acc[mf][nf], ah, bl[nf]);   // hi*lo
                mma_bf16(acc[mf][nf], al, bh[nf]);   // lo*hi
            }
        }
    }

    // ---- epilogue ----
#pragma unroll
    for (int mf = 0; mf < 4; mf++) {
        int r0 = bm + wm + mf * 16 + grp;
        int r1 = r0 + 8;
        size_t qs0 = 0, qr0 = 0, qs1 = 0, qr1 = 0;
        if (EPI == 2) {
            int t0 = r0 / E_, e0 = r0 - t0 * E_;
            int t1 = r1 / E_, e1 = r1 - t1 * E_;
            qs0 = ((size_t)t0 * N_ + send[e0]) * H_;
            qr0 = ((size_t)t0 * N_ + recv[e0]) * H_;
            qs1 = ((size_t)t1 * N_ + send[e1]) * H_;
            qr1 = ((size_t)t1 * N_ + recv[e1]) * H_;
        }
#pragma unroll
        for (int nf = 0; nf < 4; nf++) {
            int col = bn + wn + nf * 8 + 2 * q;
            float b0 = 0.f, b1 = 0.f;
            if (EPI != 0 || bias) { b0 = bias[col]; b1 = bias[col + 1]; }
            if (EPI == 0 && bias2) { b0 += bias2[col]; b1 += bias2[col + 1]; }
            float x0 = acc[mf][nf][0] + b0;
            float x1 = acc[mf][nf][1] + b1;
            float x2 = acc[mf][nf][2] + b0;
            float x3 = acc[mf][nf][3] + b1;
            if (EPI == 2) {
                x0 += Qs[qs0 + col] + Qr[qr0 + col];
                x1 += Qs[qs0 + col + 1] + Qr[qr0 + col + 1];
                x2 += Qs[qs1 + col] + Qr[qr1 + col];
                x3 += Qs[qs1 + col + 1] + Qr[qr1 + col + 1];
            }
            if (EPI >= 1) {
                x0 = eluf(x0); x1 = eluf(x1); x2 = eluf(x2); x3 = eluf(x3);
                uint32_t h01, l01, h23, l23;
                bsplit2(x0, x1, h01, l01);
                bsplit2(x2, x3, h23, l23);
                *(uint32_t*)(Ch + (size_t)r0 * 256 + col) = h01;
                *(uint32_t*)(Cl + (size_t)r0 * 256 + col) = l01;
                *(uint32_t*)(Ch + (size_t)r1 * 256 + col) = h23;
                *(uint32_t*)(Cl + (size_t)r1 * 256 + col) = l23;
            } else {
                *(float2*)(Cf + (size_t)r0 * 256 + col) = make_float2(x0, x1);
                *(float2*)(Cf + (size_t)r1 * 256 + col) = make_float2(x2, x3);
            }
        }
    }
}

// ---------------- fused bidirectional LSTM (recurrence only) ----------------
constexpr int LSTM_GROUPS = E_ / 8;
constexpr int LSTM_SMEM = 64 * 256 * 4 + 64 * 8 * 4;

__global__ __launch_bounds__(64) void lstm_kernel(
    const float* __restrict__ gf, const float* __restrict__ gr,
    const float* __restrict__ fWhh, const float* __restrict__ rWhh,
    float* __restrict__ hfOut, float* __restrict__ hrOut) {
    extern __shared__ float sm[];
    float* Wq = sm;
    float4* hsm4 = (float4*)(sm + 64 * 256);

    int dir; int grp;
    const float* gates; const float* Whh; float* hout;
    if (blockIdx.x < LSTM_GROUPS) {
        dir = 0; grp = blockIdx.x; gates = gf; Whh = fWhh; hout = hfOut;
    } else {
        dir = 1; grp = blockIdx.x - LSTM_GROUPS; gates = gr; Whh = rWhh; hout = hrOut;
    }
    const int j = threadIdx.x;

    for (int idx = j; idx < 64 * 256; idx += 64) {
        int k = idx >> 8;
        int rem = idx & 255;
        int jj = rem >> 2;
        int q = rem & 3;
        Wq[idx] = Whh[(q * 64 + jj) * 64 + k];
    }
    for (int i = j; i < 128; i += 64) hsm4[i] = make_float4(0.f, 0.f, 0.f, 0.f);

    const int e0 = grp * 8;
    float c[8];
#pragma unroll
    for (int e = 0; e < 8; e++) c[e] = 0.f;
    __syncthreads();

    for (int s = 0; s < T_; s++) {
        int t = dir ? (T_ - 1 - s) : s;
        float a0[8], a1[8], a2[8], a3[8];
#pragma unroll
        for (int e = 0; e < 8; e++) {
            const float* gp = gates + ((size_t)t * E_ + e0 + e) * 256;
            a0[e] = gp[j]; a1[e] = gp[64 + j]; a2[e] = gp[128 + j]; a3[e] = gp[192 + j];
        }
#pragma unroll 16
        for (int k = 0; k < 64; k++) {
            float4 w  = *(const float4*)&Wq[k * 256 + j * 4];
            float4 hA = hsm4[k * 2 + 0];
            float4 hB = hsm4[k * 2 + 1];
            float hv[8] = {hA.x, hA.y, hA.z, hA.w, hB.x, hB.y, hB.z, hB.w};
#pragma unroll
            for (int e = 0; e < 8; e++) {
                a0[e] = fmaf(hv[e], w.x, a0[e]);
                a1[e] = fmaf(hv[e], w.y, a1[e]);
                a2[e] = fmaf(hv[e], w.z, a2[e]);
                a3[e] = fmaf(hv[e], w.w, a3[e]);
            }
        }
        __syncthreads();
        float hn[8];
#pragma unroll
        for (int e = 0; e < 8; e++) {
            float iv = sigmf(a0[e]);
            float fv = sigmf(a1[e]);
            float gv = tanhf(a2[e]);
            float ov = sigmf(a3[e]);
            c[e] = fv * c[e] + iv * gv;
            hn[e] = ov * tanhf(c[e]);
        }
        hsm4[j * 2 + 0] = make_float4(hn[0], hn[1], hn[2], hn[3]);
        hsm4[j * 2 + 1] = make_float4(hn[4], hn[5], hn[6], hn[7]);
#pragma unroll
        for (int e = 0; e < 8; e++)
            hout[((size_t)t * E_ + e0 + e) * 64 + j] = hn[e];
        __syncthreads();
    }
}

// ---------------- output projection ----------------
__global__ void out_proj(const float* __restrict__ hf, const float* __restrict__ hr,
                         const float* __restrict__ priW, const float* __restrict__ prib,
                         const float* __restrict__ encW, const float* __restrict__ encb,
                         float* __restrict__ out) {
    int m = blockIdx.x * blockDim.x + threadIdx.x;
    if (m >= TE) return;
    const float* f = hf + (size_t)m * 64;
    const float* r = hr + (size_t)m * 64;
    float p0 = prib[0], p1 = prib[1], e0 = encb[0], e1 = encb[1];
#pragma unroll 8
    for (int k = 0; k < 64; k++) {
        float fv = f[k];
        p0 = fmaf(fv, priW[k], p0);
        p1 = fmaf(fv, priW[64 + k], p1);
        e0 = fmaf(fv, encW[k], e0);
        e1 = fmaf(fv, encW[128 + k], e1);
    }
#pragma unroll 8
    for (int k = 0; k < 64; k++) {
        float rv = r[k];
        e0 = fmaf(rv, encW[64 + k], e0);
        e1 = fmaf(rv, encW[192 + k], e1);
    }
    float4 o = make_float4(p0, p1, e0, e1);
    *(float4*)(out + (size_t)m * 4) = o;
}

// ---------------- host launch ----------------
extern "C" void kernel_launch(void* const* d_in, const int* in_sizes, int n_in,
                              void* d_out, int out_size) {
    const float* x     = (const float*)d_in[0];
    const int* send    = (const int*)d_in[2];
    const int* recv    = (const int*)d_in[3];
    const float* m1W1 = (const float*)d_in[4],  *m1b1 = (const float*)d_in[5];
    const float* m1W2 = (const float*)d_in[6],  *m1b2 = (const float*)d_in[7];
    const float* m2W1 = (const float*)d_in[8],  *m2b1 = (const float*)d_in[9];
    const float* m2W2 = (const float*)d_in[10], *m2b2 = (const float*)d_in[11];
    const float* m3W1 = (const float*)d_in[12], *m3b1 = (const float*)d_in[13];
    const float* m3W2 = (const float*)d_in[14], *m3b2 = (const float*)d_in[15];
    const float* m4W1 = (const float*)d_in[16], *m4b1 = (const float*)d_in[17];
    const float* m4W2 = (const float*)d_in[18], *m4b2 = (const float*)d_in[19];
    const float* fWih = (const float*)d_in[20], *fWhh = (const float*)d_in[21];
    const float* fbih = (const float*)d_in[22], *fbhh = (const float*)d_in[23];
    const float* rWih = (const float*)d_in[24], *rWhh = (const float*)d_in[25];
    const float* rbih = (const float*)d_in[26], *rbhh = (const float*)d_in[27];
    const float* encW = (const float*)d_in[28], *encb = (const float*)d_in[29];
    const float* priW = (const float*)d_in[30], *prib = (const float*)d_in[31];

    __nv_bfloat16 *whi, *wlo, *nbh, *nbl, *h1h, *h1l, *nsh, *nsl, *n3h, *n3l;
    __nv_bfloat16 *tmph, *tmpl, *e2h, *e2l, *e4h, *e4l;
    float *Ps, *Pr, *Qs, *Qr, *gfp, *grp_, *hfp, *hrp;
    cudaGetSymbolAddress((void**)&whi,  g_whi);
    cudaGetSymbolAddress((void**)&wlo,  g_wlo);
    cudaGetSymbolAddress((void**)&nbh,  g_nbh);
    cudaGetSymbolAddress((void**)&nbl,  g_nbl);
    cudaGetSymbolAddress((void**)&h1h,  g_h1h);
    cudaGetSymbolAddress((void**)&h1l,  g_h1l);
    cudaGetSymbolAddress((void**)&nsh,  g_nsh);
    cudaGetSymbolAddress((void**)&nsl,  g_nsl);
    cudaGetSymbolAddress((void**)&n3h,  g_n3h);
    cudaGetSymbolAddress((void**)&n3l,  g_n3l);
    cudaGetSymbolAddress((void**)&tmph, g_tmph);
    cudaGetSymbolAddress((void**)&tmpl, g_tmpl);
    cudaGetSymbolAddress((void**)&e2h,  g_e2h);
    cudaGetSymbolAddress((void**)&e2l,  g_e2l);
    cudaGetSymbolAddress((void**)&e4h,  g_e4h);
    cudaGetSymbolAddress((void**)&e4l,  g_e4l);
    cudaGetSymbolAddress((void**)&Ps,   g_Ps);
    cudaGetSymbolAddress((void**)&Pr,   g_Pr);
    cudaGetSymbolAddress((void**)&Qs,   g_Qs);
    cudaGetSymbolAddress((void**)&Qr,   g_Qr);
    cudaGetSymbolAddress((void**)&gfp,  g_gf);
    cudaGetSymbolAddress((void**)&grp_, g_gr);
    cudaGetSymbolAddress((void**)&hfp,  g_hf);
    cudaGetSymbolAddress((void**)&hrp,  g_hr);

    cudaFuncSetAttribute(lstm_kernel, cudaFuncAttributeMaxDynamicSharedMemorySize, LSTM_SMEM);

    build_rlist<<<1, 64>>>(recv);

    // one fused split of all 12 weight segments (each 256 rows x 256 k)
    SplitArgs sa;
    sa.s[0]  = {m1W2, 256, 0};
    sa.s[1]  = {m2W1, 512, 0};      // Ws
    sa.s[2]  = {m2W1, 512, 256};    // Wr
    sa.s[3]  = {m2W2, 256, 0};
    sa.s[4]  = {m3W1, 256, 0};
    sa.s[5]  = {m3W2, 256, 0};
    sa.s[6]  = {m4W1, 768, 0};      // Q_s weights
    sa.s[7]  = {m4W1, 768, 256};    // Q_r weights
    sa.s[8]  = {m4W1, 768, 512};    // skip weights
    sa.s[9]  = {m4W2, 256, 0};
    sa.s[10] = {fWih, 256, 0};
    sa.s[11] = {rWih, 256, 0};
    split_all<<<dim3(256, NSEG), 256>>>(sa, whi, wlo);

    const dim3 gN(2, TN / 128);     // node-level GEMMs (M=2560)
    const dim3 gE(2, TE / 128);     // edge-level GEMMs (M=99840)

    // mlp1
    mlp1_fc1<<<TN * H_ / 256, 256>>>(x, m1W1, m1b1);
    gemm_tc<1><<<gN, 256>>>(nbh, nbl, whi + 0 * SEGSZ, wlo + 0 * SEGSZ,
        m1b2, nullptr, nullptr, h1h, h1l, nullptr, nullptr, nullptr, nullptr);
    // mlp2 fc1 via node products: Ps = h1@Ws + m2b1, Pr = h1@Wr
    gemm_tc<0><<<gN, 256>>>(h1h, h1l, whi + 1 * SEGSZ, wlo + 1 * SEGSZ,
        m2b1, nullptr, Ps, nullptr, nullptr, nullptr, nullptr, nullptr, nullptr);
    gemm_tc<0><<<gN, 256>>>(h1h, h1l, whi + 2 * SEGSZ, wlo + 2 * SEGSZ,
        nullptr, nullptr, Pr, nullptr, nullptr, nullptr, nullptr, nullptr, nullptr);
    combine2<<<TE, 256>>>(Ps, Pr, tmph, tmpl, send, recv);
    // mlp2 fc2 (edge GEMM)
    gemm_tc<1><<<gE, 256>>>(tmph, tmpl, whi + 3 * SEGSZ, wlo + 3 * SEGSZ,
        m2b2, nullptr, nullptr, e2h, e2l, nullptr, nullptr, nullptr, nullptr);
    // edge2node + mlp3 (node GEMMs)
    edge2node<<<TN, 256>>>();
    gemm_tc<1><<<gN, 256>>>(nsh, nsl, whi + 4 * SEGSZ, wlo + 4 * SEGSZ,
        m3b1, nullptr, nullptr, nbh, nbl, nullptr, nullptr, nullptr, nullptr);
    gemm_tc<1><<<gN, 256>>>(nbh, nbl, whi + 5 * SEGSZ, wlo + 5 * SEGSZ,
        m3b2, nullptr, nullptr, n3h, n3l, nullptr, nullptr, nullptr, nullptr);
    // mlp4 fc1: node products Qs, Qr + skip edge GEMM with fused gather-add epilogue
    gemm_tc<0><<<gN, 256>>>(n3h, n3l, whi + 6 * SEGSZ, wlo + 6 * SEGSZ,
        nullptr, nullptr, Qs, nullptr, nullptr, nullptr, nullptr, nullptr, nullptr);
    gemm_tc<0><<<gN, 256>>>(n3h, n3l, whi + 7 * SEGSZ, wlo + 7 * SEGSZ,
        nullptr, nullptr, Qr, nullptr, nullptr, nullptr, nullptr, nullptr, nullptr);
    gemm_tc<2><<<gE, 256>>>(e2h, e2l, whi + 8 * SEGSZ, wlo + 8 * SEGSZ,
        m4b1, nullptr, nullptr, tmph, tmpl, send, recv, Qs, Qr);
    // mlp4 fc2 (edge GEMM)
    gemm_tc<1><<<gE, 256>>>(tmph, tmpl, whi + 9 * SEGSZ, wlo + 9 * SEGSZ,
        m4b2, nullptr, nullptr, e4h, e4l, nullptr, nullptr, nullptr, nullptr);
    // LSTM input projections (fp32 out, both biases folded)
    gemm_tc<0><<<gE, 256>>>(e4h, e4l, whi + 10 * SEGSZ, wlo + 10 * SEGSZ,
        fbih, fbhh, gfp, nullptr, nullptr, nullptr, nullptr, nullptr, nullptr);
    gemm_tc<0><<<gE, 256>>>(e4h, e4l, whi + 11 * SEGSZ, wlo + 11 * SEGSZ,
        rbih, rbhh, grp_, nullptr, nullptr, nullptr, nullptr, nullptr, nullptr);
    // recurrence
    lstm_kernel<<<2 * LSTM_GROUPS, 64, LSTM_SMEM>>>(gfp, grp_, fWhh, rWhh, hfp, hrp);
    // outputs
    out_proj<<<TE / 256, 256>>>(hfp, hrp, priW, prib, encW, encb, (float*)d_out);
}

// round 9
// speedup vs baseline: 1.5217x; 1.0987x over previous
#include <cuda_runtime.h>
#include <cuda_bf16.h>
#include <cstdint>

// ---------------- problem constants ----------------
constexpr int T_ = 64, N_ = 40, D_ = 4, H_ = 256, R_ = 64;
constexpr int E_ = N_ * (N_ - 1);        // 1560
constexpr int TE = T_ * E_;              // 99840
constexpr int TN = T_ * N_;              // 2560

// ---------------- scratch ----------------
__device__ __align__(16) __nv_bfloat16 g_nbh[TN * H_], g_nbl[TN * H_];
__device__ __align__(16) __nv_bfloat16 g_h1h[TN * H_], g_h1l[TN * H_];
__device__ __align__(16) __nv_bfloat16 g_nsh[TN * H_], g_nsl[TN * H_];
__device__ __align__(16) __nv_bfloat16 g_n3h[TN * H_], g_n3l[TN * H_];
__device__ __align__(16) __nv_bfloat16 g_tmph[TE * H_], g_tmpl[TE * H_];
__device__ __align__(16) __nv_bfloat16 g_e2h[TE * H_], g_e2l[TE * H_];
__device__ __align__(16) __nv_bfloat16 g_e4h[TE * H_], g_e4l[TE * H_];
// fused node-level fp32 partials: [node][512] (first 256 = send-proj, last 256 = recv-proj)
__device__ __align__(16) float g_P[TN * 512];
__device__ __align__(16) float g_Q[TN * 512];
// fused LSTM gate buffer: [edge-row][512] (cols 0-255 fwd, 256-511 rev)
__device__ __align__(16) float g_g[(size_t)TE * 512];
// split weight arena: 12 segments of 65536 (each 256 rows x 256 k)
constexpr int NSEG = 12;
constexpr int SEGSZ = 65536;
__device__ __align__(16) __nv_bfloat16 g_whi[NSEG * SEGSZ], g_wlo[NSEG * SEGSZ];
__device__ float g_hf[TE * R_];
__device__ float g_hr[TE * R_];
__device__ int   g_rlist[N_ * (N_ - 1)];

__device__ __forceinline__ float eluf(float v) { return v > 0.f ? v : expm1f(v); }
__device__ __forceinline__ float sigmf(float v) { return 1.f / (1.f + expf(-v)); }

__device__ __forceinline__ void bsplit2(float x0, float x1, uint32_t& hi, uint32_t& lo) {
    asm("cvt.rn.bf16x2.f32 %0, %1, %2;" : "=r"(hi) : "f"(x1), "f"(x0));
    __nv_bfloat162 h = *reinterpret_cast<__nv_bfloat162*>(&hi);
    float r0 = x0 - __bfloat162float(h.x);
    float r1 = x1 - __bfloat162float(h.y);
    asm("cvt.rn.bf16x2.f32 %0, %1, %2;" : "=r"(lo) : "f"(r1), "f"(r0));
}

__device__ __forceinline__ void mma_bf16(float* d, const uint32_t* a, const uint32_t* b) {
    asm volatile(
        "mma.sync.aligned.m16n8k16.row.col.f32.bf16.bf16.f32 "
        "{%0,%1,%2,%3},{%4,%5,%6,%7},{%8,%9},{%0,%1,%2,%3};"
        : "+f"(d[0]), "+f"(d[1]), "+f"(d[2]), "+f"(d[3])
        : "r"(a[0]), "r"(a[1]), "r"(a[2]), "r"(a[3]), "r"(b[0]), "r"(b[1]));
}

__device__ __forceinline__ void ldsm4(uint32_t* r, uint32_t addr) {
    asm volatile("ldmatrix.sync.aligned.m8n8.x4.shared.b16 {%0,%1,%2,%3}, [%4];"
                 : "=r"(r[0]), "=r"(r[1]), "=r"(r[2]), "=r"(r[3]) : "r"(addr));
}

__device__ __forceinline__ uint32_t smem_u32(const void* p) {
    uint32_t a;
    asm("{ .reg .u64 t; cvta.to.shared.u64 t, %1; cvt.u32.u64 %0, t; }" : "=r"(a) : "l"(p));
    return a;
}

// ---------------- fused weight split ----------------
struct SplitSeg { const float* src; int stride; int coff; };
struct SplitArgs { SplitSeg s[NSEG]; };

__global__ void split_all(SplitArgs a, __nv_bfloat16* __restrict__ oh,
                          __nv_bfloat16* __restrict__ ol) {
    int seg = blockIdx.y;
    int idx = blockIdx.x * 256 + threadIdx.x;
    int j = idx >> 8, k = idx & 255;
    const SplitSeg s = a.s[seg];
    float v = s.src[j * s.stride + s.coff + k];
    __nv_bfloat16 h = __float2bfloat16(v);
    int o = seg * SEGSZ + idx;
    oh[o] = h;
    ol[o] = __float2bfloat16(v - __bfloat162float(h));
}

// ---------------- mlp1 fc1 (K=4, tiny) -> split out ----------------
__global__ void mlp1_fc1(const float* __restrict__ x, const float* __restrict__ W1,
                         const float* __restrict__ b1) {
    int idx = blockIdx.x * blockDim.x + threadIdx.x;
    int row = idx >> 8;
    int j = idx & 255;
    const float* xr = x + row * D_;
    const float* w = W1 + j * D_;
    float v = b1[j] + xr[0] * w[0] + xr[1] * w[1] + xr[2] * w[2] + xr[3] * w[3];
    v = eluf(v);
    __nv_bfloat16 h = __float2bfloat16(v);
    g_nbh[idx] = h;
    g_nbl[idx] = __float2bfloat16(v - __bfloat162float(h));
}

// ---------------- build per-node incoming edge lists ----------------
__global__ void build_rlist(const int* __restrict__ recv) {
    int n = threadIdx.x;
    if (n >= N_) return;
    int p = 0;
    for (int e = 0; e < E_; e++)
        if (recv[e] == n) g_rlist[n * (N_ - 1) + p++] = e;
}

// ---------------- edge2node scatter-add ----------------
__global__ void edge2node() {
    int b = blockIdx.x;
    int t = b / N_;
    int n = b - t * N_;
    int c = threadIdx.x;
    const int* lst = g_rlist + n * (N_ - 1);
    float s = 0.f;
#pragma unroll 13
    for (int i = 0; i < N_ - 1; i++) {
        int e = lst[i];
        size_t idx = ((size_t)t * E_ + e) * H_ + c;
        s += __bfloat162float(g_e2h[idx]) + __bfloat162float(g_e2l[idx]);
    }
    __nv_bfloat16 h = __float2bfloat16(s);
    g_nsh[(size_t)b * H_ + c] = h;
    g_nsl[(size_t)b * H_ + c] = __float2bfloat16(s - __bfloat162float(h));
}

// ---------------- mlp2-fc1 combine: elu(P[send, 0:256] + P[recv, 256:512] + b) ----------------
__global__ void combine2(const float* __restrict__ P, const float* __restrict__ b,
                         __nv_bfloat16* __restrict__ oh, __nv_bfloat16* __restrict__ ol,
                         const int* __restrict__ send, const int* __restrict__ recv) {
    int m = blockIdx.x;
    int c = threadIdx.x;
    int t = m / E_;
    int e = m - t * E_;
    float v = P[((size_t)t * N_ + send[e]) * 512 + c]
            + P[((size_t)t * N_ + recv[e]) * 512 + 256 + c] + b[c];
    v = eluf(v);
    __nv_bfloat16 h = __float2bfloat16(v);
    oh[(size_t)m * H_ + c] = h;
    ol[(size_t)m * H_ + c] = __float2bfloat16(v - __bfloat162float(h));
}

// ------- bf16x3 tensor-core GEMM: 128x128 tiles, LDSM fragments, K=256 -------
// EPI 0: fp32 out (no bias). EPI 1: +b0, ELU, split bf16 out.
// EPI 2: +b0 + Q[send,0:256]+Q[recv,256:512] gather, ELU, split bf16 out.
// EPI 3: fp32 out, col<256 ? b0+b1 : b2+b3 (fused LSTM projections).
// smem: 4 tiles of 128 rows x 48B (32B data + 16B pad) = 24576B. 2 CTAs/SM.
template <int EPI>
__global__ __launch_bounds__(256, 2) void gemm_tc(
    const __nv_bfloat16* __restrict__ Ah, const __nv_bfloat16* __restrict__ Al,
    const __nv_bfloat16* __restrict__ Wh, const __nv_bfloat16* __restrict__ Wl,
    const float* __restrict__ b0p, const float* __restrict__ b1p,
    const float* __restrict__ b2p, const float* __restrict__ b3p,
    float* __restrict__ Cf, __nv_bfloat16* __restrict__ Ch, __nv_bfloat16* __restrict__ Cl,
    int ldc,
    const int* __restrict__ send, const int* __restrict__ recv,
    const float* __restrict__ Q) {
    __shared__ __align__(16) char smem[24576];
    const uint32_t sb = smem_u32(smem);
    const int tid = threadIdx.x;
    const int bm = blockIdx.y * 128;
    const int bn = blockIdx.x * 128;
    const int warp = tid >> 5, lane = tid & 31;

    // load roles: thread -> (tile row, 16B half of 32B k-chunk)
    const int row = tid & 127;
    const int half = tid >> 7;
    const __nv_bfloat16* arh = Ah + (size_t)(bm + row) * H_ + half * 8;
    const __nv_bfloat16* arl = Al + (size_t)(bm + row) * H_ + half * 8;
    const __nv_bfloat16* wrh = Wh + (size_t)(bn + row) * H_ + half * 8;
    const __nv_bfloat16* wrl = Wl + (size_t)(bn + row) * H_ + half * 8;
    char* sts = smem + row * 48 + half * 16;

    // ldmatrix addressing (validated in R5): lanes 0-15 -> rows, lanes 16-31 -> +16B
    const int wm = (warp >> 2) * 64, wn = (warp & 3) * 32;
    const int lrow = lane & 15, lkh = lane >> 4;
    const uint32_t abase = sb + (uint32_t)((wm + lrow) * 48 + lkh * 16);
    const uint32_t bbase = sb + 12288u + (uint32_t)((wn + lrow) * 48 + lkh * 16);

    float acc[4][4][4] = {};

    uint4 vah, vaL, vwh, vwL;
    auto load_g = [&](int kt) {
        vah = *(const uint4*)(arh + kt);
        vaL = *(const uint4*)(arl + kt);
        vwh = *(const uint4*)(wrh + kt);
        vwL = *(const uint4*)(wrl + kt);
    };
    load_g(0);

#pragma unroll 1
    for (int step = 0; step < 16; step++) {
        __syncthreads();
        *(uint4*)(sts + 0)     = vah;   // A hi
        *(uint4*)(sts + 6144)  = vaL;   // A lo
        *(uint4*)(sts + 12288) = vwh;   // W hi
        *(uint4*)(sts + 18432) = vwL;   // W lo
        __syncthreads();
        if (step < 15) load_g((step + 1) * 16);

        uint32_t ah[4][4], al[4][4], bh[2][4], bl[2][4];
#pragma unroll
        for (int mf = 0; mf < 4; mf++) {
            ldsm4(ah[mf], abase + mf * 768u);
            ldsm4(al[mf], abase + mf * 768u + 6144u);
        }
#pragma unroll
        for (int p = 0; p < 2; p++) {
            ldsm4(bh[p], bbase + p * 768u);
            ldsm4(bl[p], bbase + p * 768u + 6144u);
        }
#pragma unroll
        for (int mf = 0; mf < 4; mf++) {
#pragma unroll
            for (int nf = 0; nf < 4; nf++) {
                const int p = nf >> 1, o = nf & 1;
                uint32_t bhf[2] = {bh[p][o], bh[p][o + 2]};
                uint32_t blf[2] = {bl[p][o], bl[p][o + 2]};
                mma_bf16(acc[mf][nf], ah[mf], bhf);   // hi*hi
                mma_bf16(acc[mf][nf], ah[mf], blf);   // hi*lo
                mma_bf16(acc[mf][nf], al[mf], bhf);   // lo*hi
            }
        }
    }

    // ---- epilogue ----
    const int grp = lane >> 2, q = lane & 3;
#pragma unroll
    for (int mf = 0; mf < 4; mf++) {
        int r0 = bm + wm + mf * 16 + grp;
        int r1 = r0 + 8;
        size_t qs0 = 0, qr0 = 0, qs1 = 0, qr1 = 0;
        if (EPI == 2) {
            int t0 = r0 / E_, e0 = r0 - t0 * E_;
            int t1 = r1 / E_, e1 = r1 - t1 * E_;
            qs0 = ((size_t)t0 * N_ + send[e0]) * 512;
            qr0 = ((size_t)t0 * N_ + recv[e0]) * 512 + 256;
            qs1 = ((size_t)t1 * N_ + send[e1]) * 512;
            qr1 = ((size_t)t1 * N_ + recv[e1]) * 512 + 256;
        }
#pragma unroll
        for (int nf = 0; nf < 4; nf++) {
            int col = bn + wn + nf * 8 + 2 * q;
            float b0 = 0.f, b1 = 0.f;
            if (EPI == 1 || EPI == 2) { b0 = b0p[col]; b1 = b0p[col + 1]; }
            if (EPI == 3) {
                if (col < 256) { b0 = b0p[col] + b1p[col]; b1 = b0p[col + 1] + b1p[col + 1]; }
                else { b0 = b2p[col - 256] + b3p[col - 256]; b1 = b2p[col - 255] + b3p[col - 255]; }
            }
            float x0 = acc[mf][nf][0] + b0;
            float x1 = acc[mf][nf][1] + b1;
            float x2 = acc[mf][nf][2] + b0;
            float x3 = acc[mf][nf][3] + b1;
            if (EPI == 2) {
                x0 += Q[qs0 + col] + Q[qr0 + col];
                x1 += Q[qs0 + col + 1] + Q[qr0 + col + 1];
                x2 += Q[qs1 + col] + Q[qr1 + col];
                x3 += Q[qs1 + col + 1] + Q[qr1 + col + 1];
            }
            if (EPI == 1 || EPI == 2) {
                x0 = eluf(x0); x1 = eluf(x1); x2 = eluf(x2); x3 = eluf(x3);
                uint32_t h01, l01, h23, l23;
                bsplit2(x0, x1, h01, l01);
                bsplit2(x2, x3, h23, l23);
                *(uint32_t*)(Ch + (size_t)r0 * 256 + col) = h01;
                *(uint32_t*)(Cl + (size_t)r0 * 256 + col) = l01;
                *(uint32_t*)(Ch + (size_t)r1 * 256 + col) = h23;
                *(uint32_t*)(Cl + (size_t)r1 * 256 + col) = l23;
            } else {
                *(float2*)(Cf + (size_t)r0 * ldc + col) = make_float2(x0, x1);
                *(float2*)(Cf + (size_t)r1 * ldc + col) = make_float2(x2, x3);
            }
        }
    }
}

// ---------------- fused bidirectional LSTM (gates in [TE][512] buffer) ----------------
constexpr int LSTM_GROUPS = E_ / 8;
constexpr int LSTM_SMEM = 64 * 256 * 4 + 64 * 8 * 4;

__global__ __launch_bounds__(64) void lstm_kernel(
    const float* __restrict__ gates,
    const float* __restrict__ fWhh, const float* __restrict__ rWhh,
    float* __restrict__ hfOut, float* __restrict__ hrOut) {
    extern __shared__ float sm[];
    float* Wq = sm;
    float4* hsm4 = (float4*)(sm + 64 * 256);

    int dir; int grp;
    const float* Whh; float* hout;
    if (blockIdx.x < LSTM_GROUPS) {
        dir = 0; grp = blockIdx.x; Whh = fWhh; hout = hfOut;
    } else {
        dir = 1; grp = blockIdx.x - LSTM_GROUPS; Whh = rWhh; hout = hrOut;
    }
    const int doff = dir * 256;
    const int j = threadIdx.x;

    for (int idx = j; idx < 64 * 256; idx += 64) {
        int k = idx >> 8;
        int rem = idx & 255;
        int jj = rem >> 2;
        int q = rem & 3;
        Wq[idx] = Whh[(q * 64 + jj) * 64 + k];
    }
    for (int i = j; i < 128; i += 64) hsm4[i] = make_float4(0.f, 0.f, 0.f, 0.f);

    const int e0 = grp * 8;
    float c[8];
#pragma unroll
    for (int e = 0; e < 8; e++) c[e] = 0.f;
    __syncthreads();

    for (int s = 0; s < T_; s++) {
        int t = dir ? (T_ - 1 - s) : s;
        float a0[8], a1[8], a2[8], a3[8];
#pragma unroll
        for (int e = 0; e < 8; e++) {
            const float* gp = gates + ((size_t)t * E_ + e0 + e) * 512 + doff;
            a0[e] = gp[j]; a1[e] = gp[64 + j]; a2[e] = gp[128 + j]; a3[e] = gp[192 + j];
        }
#pragma unroll 16
        for (int k = 0; k < 64; k++) {
            float4 w  = *(const float4*)&Wq[k * 256 + j * 4];
            float4 hA = hsm4[k * 2 + 0];
            float4 hB = hsm4[k * 2 + 1];
            float hv[8] = {hA.x, hA.y, hA.z, hA.w, hB.x, hB.y, hB.z, hB.w};
#pragma unroll
            for (int e = 0; e < 8; e++) {
                a0[e] = fmaf(hv[e], w.x, a0[e]);
                a1[e] = fmaf(hv[e], w.y, a1[e]);
                a2[e] = fmaf(hv[e], w.z, a2[e]);
                a3[e] = fmaf(hv[e], w.w, a3[e]);
            }
        }
        __syncthreads();
        float hn[8];
#pragma unroll
        for (int e = 0; e < 8; e++) {
            float iv = sigmf(a0[e]);
            float fv = sigmf(a1[e]);
            float gv = tanhf(a2[e]);
            float ov = sigmf(a3[e]);
            c[e] = fv * c[e] + iv * gv;
            hn[e] = ov * tanhf(c[e]);
        }
        hsm4[j * 2 + 0] = make_float4(hn[0], hn[1], hn[2], hn[3]);
        hsm4[j * 2 + 1] = make_float4(hn[4], hn[5], hn[6], hn[7]);
#pragma unroll
        for (int e = 0; e < 8; e++)
            hout[((size_t)t * E_ + e0 + e) * 64 + j] = hn[e];
        __syncthreads();
    }
}

// ---------------- output projection ----------------
__global__ void out_proj(const float* __restrict__ hf, const float* __restrict__ hr,
                         const float* __restrict__ priW, const float* __restrict__ prib,
                         const float* __restrict__ encW, const float* __restrict__ encb,
                         float* __restrict__ out) {
    int m = blockIdx.x * blockDim.x + threadIdx.x;
    if (m >= TE) return;
    const float* f = hf + (size_t)m * 64;
    const float* r = hr + (size_t)m * 64;
    float p0 = prib[0], p1 = prib[1], e0 = encb[0], e1 = encb[1];
#pragma unroll 8
    for (int k = 0; k < 64; k++) {
        float fv = f[k];
        p0 = fmaf(fv, priW[k], p0);
        p1 = fmaf(fv, priW[64 + k], p1);
        e0 = fmaf(fv, encW[k], e0);
        e1 = fmaf(fv, encW[128 + k], e1);
    }
#pragma unroll 8
    for (int k = 0; k < 64; k++) {
        float rv = r[k];
        e0 = fmaf(rv, encW[64 + k], e0);
        e1 = fmaf(rv, encW[192 + k], e1);
    }
    float4 o = make_float4(p0, p1, e0, e1);
    *(float4*)(out + (size_t)m * 4) = o;
}

// ---------------- host launch ----------------
extern "C" void kernel_launch(void* const* d_in, const int* in_sizes, int n_in,
                              void* d_out, int out_size) {
    const float* x     = (const float*)d_in[0];
    const int* send    = (const int*)d_in[2];
    const int* recv    = (const int*)d_in[3];
    const float* m1W1 = (const float*)d_in[4],  *m1b1 = (const float*)d_in[5];
    const float* m1W2 = (const float*)d_in[6],  *m1b2 = (const float*)d_in[7];
    const float* m2W1 = (const float*)d_in[8],  *m2b1 = (const float*)d_in[9];
    const float* m2W2 = (const float*)d_in[10], *m2b2 = (const float*)d_in[11];
    const float* m3W1 = (const float*)d_in[12], *m3b1 = (const float*)d_in[13];
    const float* m3W2 = (const float*)d_in[14], *m3b2 = (const float*)d_in[15];
    const float* m4W1 = (const float*)d_in[16], *m4b1 = (const float*)d_in[17];
    const float* m4W2 = (const float*)d_in[18], *m4b2 = (const float*)d_in[19];
    const float* fWih = (const float*)d_in[20], *fWhh = (const float*)d_in[21];
    const float* fbih = (const float*)d_in[22], *fbhh = (const float*)d_in[23];
    const float* rWih = (const float*)d_in[24], *rWhh = (const float*)d_in[25];
    const float* rbih = (const float*)d_in[26], *rbhh = (const float*)d_in[27];
    const float* encW = (const float*)d_in[28], *encb = (const float*)d_in[29];
    const float* priW = (const float*)d_in[30], *prib = (const float*)d_in[31];

    __nv_bfloat16 *whi, *wlo, *nbh, *nbl, *h1h, *h1l, *nsh, *nsl, *n3h, *n3l;
    __nv_bfloat16 *tmph, *tmpl, *e2h, *e2l, *e4h, *e4l;
    float *P, *Q, *gg, *hfp, *hrp;
    cudaGetSymbolAddress((void**)&whi,  g_whi);
    cudaGetSymbolAddress((void**)&wlo,  g_wlo);
    cudaGetSymbolAddress((void**)&nbh,  g_nbh);
    cudaGetSymbolAddress((void**)&nbl,  g_nbl);
    cudaGetSymbolAddress((void**)&h1h,  g_h1h);
    cudaGetSymbolAddress((void**)&h1l,  g_h1l);
    cudaGetSymbolAddress((void**)&nsh,  g_nsh);
    cudaGetSymbolAddress((void**)&nsl,  g_nsl);
    cudaGetSymbolAddress((void**)&n3h,  g_n3h);
    cudaGetSymbolAddress((void**)&n3l,  g_n3l);
    cudaGetSymbolAddress((void**)&tmph, g_tmph);
    cudaGetSymbolAddress((void**)&tmpl, g_tmpl);
    cudaGetSymbolAddress((void**)&e2h,  g_e2h);
    cudaGetSymbolAddress((void**)&e2l,  g_e2l);
    cudaGetSymbolAddress((void**)&e4h,  g_e4h);
    cudaGetSymbolAddress((void**)&e4l,  g_e4l);
    cudaGetSymbolAddress((void**)&P,    g_P);
    cudaGetSymbolAddress((void**)&Q,    g_Q);
    cudaGetSymbolAddress((void**)&gg,   g_g);
    cudaGetSymbolAddress((void**)&hfp,  g_hf);
    cudaGetSymbolAddress((void**)&hrp,  g_hr);

    cudaFuncSetAttribute(lstm_kernel, cudaFuncAttributeMaxDynamicSharedMemorySize, LSTM_SMEM);

    build_rlist<<<1, 64>>>(recv);

    SplitArgs sa;
    sa.s[0]  = {m1W2, 256, 0};
    sa.s[1]  = {m2W1, 512, 0};      // Ws
    sa.s[2]  = {m2W1, 512, 256};    // Wr
    sa.s[3]  = {m2W2, 256, 0};
    sa.s[4]  = {m3W1, 256, 0};
    sa.s[5]  = {m3W2, 256, 0};
    sa.s[6]  = {m4W1, 768, 0};      // Qs weights
    sa.s[7]  = {m4W1, 768, 256};    // Qr weights
    sa.s[8]  = {m4W1, 768, 512};    // skip weights
    sa.s[9]  = {m4W2, 256, 0};
    sa.s[10] = {fWih, 256, 0};
    sa.s[11] = {rWih, 256, 0};
    split_all<<<dim3(256, NSEG), 256>>>(sa, whi, wlo);

    const dim3 gN(2, TN / 128);      // node GEMM, N=256
    const dim3 gN2(4, TN / 128);     // node GEMM, N=512 (fused)
    const dim3 gE(2, TE / 128);      // edge GEMM, N=256
    const dim3 gE2(4, TE / 128);     // edge GEMM, N=512 (fused)

    // mlp1
    mlp1_fc1<<<TN * H_ / 256, 256>>>(x, m1W1, m1b1);
    gemm_tc<1><<<gN, 256>>>(nbh, nbl, whi + 0 * SEGSZ, wlo + 0 * SEGSZ,
        m1b2, nullptr, nullptr, nullptr, nullptr, h1h, h1l, 256, nullptr, nullptr, nullptr);
    // mlp2 fc1: fused node products P = h1 @ [Ws|Wr]
    gemm_tc<0><<<gN2, 256>>>(h1h, h1l, whi + 1 * SEGSZ, wlo + 1 * SEGSZ,
        nullptr, nullptr, nullptr, nullptr, P, nullptr, nullptr, 512, nullptr, nullptr, nullptr);
    combine2<<<TE, 256>>>(P, m2b1, tmph, tmpl, send, recv);
    // mlp2 fc2
    gemm_tc<1><<<gE, 256>>>(tmph, tmpl, whi + 3 * SEGSZ, wlo + 3 * SEGSZ,
        m2b2, nullptr, nullptr, nullptr, nullptr, e2h, e2l, 256, nullptr, nullptr, nullptr);
    // edge2node + mlp3
    edge2node<<<TN, 256>>>();
    gemm_tc<1><<<gN, 256>>>(nsh, nsl, whi + 4 * SEGSZ, wlo + 4 * SEGSZ,
        m3b1, nullptr, nullptr, nullptr, nullptr, nbh, nbl, 256, nullptr, nullptr, nullptr);
    gemm_tc<1><<<gN, 256>>>(nbh, nbl, whi + 5 * SEGSZ, wlo + 5 * SEGSZ,
        m3b2, nullptr, nullptr, nullptr, nullptr, n3h, n3l, 256, nullptr, nullptr, nullptr);
    // mlp4 fc1: fused node products Q = n3 @ [Wqs|Wqr], then skip GEMM w/ gather epilogue
    gemm_tc<0><<<gN2, 256>>>(n3h, n3l, whi + 6 * SEGSZ, wlo + 6 * SEGSZ,
        nullptr, nullptr, nullptr, nullptr, Q, nullptr, nullptr, 512, nullptr, nullptr, nullptr);
    gemm_tc<2><<<gE, 256>>>(e2h, e2l, whi + 8 * SEGSZ, wlo + 8 * SEGSZ,
        m4b1, nullptr, nullptr, nullptr, nullptr, tmph, tmpl, 256, send, recv, Q);
    // mlp4 fc2
    gemm_tc<1><<<gE, 256>>>(tmph, tmpl, whi + 9 * SEGSZ, wlo + 9 * SEGSZ,
        m4b2, nullptr, nullptr, nullptr, nullptr, e4h, e4l, 256, nullptr, nullptr, nullptr);
    // fused LSTM input projections -> g_g [TE][512]
    gemm_tc<3><<<gE2, 256>>>(e4h, e4l, whi + 10 * SEGSZ, wlo + 10 * SEGSZ,
        fbih, fbhh, rbih, rbhh, gg, nullptr, nullptr, 512, nullptr, nullptr, nullptr);
    // recurrence
    lstm_kernel<<<2 * LSTM_GROUPS, 64, LSTM_SMEM>>>(gg, fWhh, rWhh, hfp, hrp);
    // outputs
    out_proj<<<TE / 256, 256>>>(hfp, hrp, priW, prib, encW, encb, (float*)d_out);
}